// round 10
// baseline (speedup 1.0000x reference)
#include <cuda_runtime.h>
#include <cuda_bf16.h>
#include <cstdint>

#define Bn 2
#define Sn 2048
#define Dn 1024
#define Hn 16
#define DKn 64

#define NELEM (4096 * 1024)
#define WELEM (1024 * 1024)

// bf16 hi/lo scratch (device globals; no allocations allowed)
__device__ __nv_bfloat16 g_xqh[NELEM], g_xql[NELEM];
__device__ __nv_bfloat16 g_xkh[NELEM], g_xkl[NELEM];
__device__ __nv_bfloat16 g_xvh[NELEM], g_xvl[NELEM];
__device__ __nv_bfloat16 g_wqh[WELEM], g_wql[WELEM];
__device__ __nv_bfloat16 g_wkh[WELEM], g_wkl[WELEM];
__device__ __nv_bfloat16 g_wvh[WELEM], g_wvl[WELEM];
__device__ __nv_bfloat16 g_woh[WELEM], g_wol[WELEM];
__device__ __nv_bfloat16 g_Qh[NELEM], g_Ql[NELEM];   // [B,H,S,DK] (pre-scaled)
__device__ __nv_bfloat16 g_Kh[NELEM], g_Kl[NELEM];
__device__ __nv_bfloat16 g_Vh[NELEM], g_Vl[NELEM];
__device__ __nv_bfloat16 g_Ah[NELEM], g_Al[NELEM];   // [B,S,D]

// ---------------------------------------------------------------------------
// Helpers
// ---------------------------------------------------------------------------
__device__ __forceinline__ uint32_t smem_u32(const void* p) {
    uint32_t a;
    asm("{ .reg .u64 t; cvta.to.shared.u64 t, %1; cvt.u32.u64 %0, t; }"
        : "=r"(a) : "l"(p));
    return a;
}

__device__ __forceinline__ void ldsm_x4(uint32_t (&r)[4], uint32_t addr) {
    asm volatile("ldmatrix.sync.aligned.m8n8.x4.shared.b16 {%0,%1,%2,%3}, [%4];"
        : "=r"(r[0]), "=r"(r[1]), "=r"(r[2]), "=r"(r[3]) : "r"(addr));
}

__device__ __forceinline__ void ldsm_x4_t(uint32_t (&r)[4], uint32_t addr) {
    asm volatile("ldmatrix.sync.aligned.m8n8.x4.trans.shared.b16 {%0,%1,%2,%3}, [%4];"
        : "=r"(r[0]), "=r"(r[1]), "=r"(r[2]), "=r"(r[3]) : "r"(addr));
}

__device__ __forceinline__ void mma16816(float (&d)[4], const uint32_t (&a)[4],
                                         uint32_t b0, uint32_t b1) {
    asm volatile(
        "mma.sync.aligned.m16n8k16.row.col.f32.bf16.bf16.f32 "
        "{%0,%1,%2,%3}, {%4,%5,%6,%7}, {%8,%9}, {%0,%1,%2,%3};"
        : "+f"(d[0]), "+f"(d[1]), "+f"(d[2]), "+f"(d[3])
        : "r"(a[0]), "r"(a[1]), "r"(a[2]), "r"(a[3]), "r"(b0), "r"(b1));
}

#define CP_ASYNC16(dst, src) \
    asm volatile("cp.async.cg.shared.global [%0], [%1], 16;" \
                 :: "r"(dst), "l"(src) : "memory")
#define CP_COMMIT()  asm volatile("cp.async.commit_group;" ::: "memory")
#define CP_WAIT0()   asm volatile("cp.async.wait_group 0;" ::: "memory")
#define CP_WAIT1()   asm volatile("cp.async.wait_group 1;" ::: "memory")

__device__ __forceinline__ void split4(float4 v, uint2& hi, uint2& lo) {
    __nv_bfloat16 h0 = __float2bfloat16_rn(v.x);
    __nv_bfloat16 h1 = __float2bfloat16_rn(v.y);
    __nv_bfloat16 h2 = __float2bfloat16_rn(v.z);
    __nv_bfloat16 h3 = __float2bfloat16_rn(v.w);
    __nv_bfloat16 l0 = __float2bfloat16_rn(v.x - __bfloat162float(h0));
    __nv_bfloat16 l1 = __float2bfloat16_rn(v.y - __bfloat162float(h1));
    __nv_bfloat16 l2 = __float2bfloat16_rn(v.z - __bfloat162float(h2));
    __nv_bfloat16 l3 = __float2bfloat16_rn(v.w - __bfloat162float(h3));
    hi.x = ((uint32_t)__bfloat16_as_ushort(h1) << 16) | __bfloat16_as_ushort(h0);
    hi.y = ((uint32_t)__bfloat16_as_ushort(h3) << 16) | __bfloat16_as_ushort(h2);
    lo.x = ((uint32_t)__bfloat16_as_ushort(l1) << 16) | __bfloat16_as_ushort(l0);
    lo.y = ((uint32_t)__bfloat16_as_ushort(l3) << 16) | __bfloat16_as_ushort(l2);
}

__device__ __forceinline__ void split2(float a, float b, uint32_t& hi, uint32_t& lo) {
    __nv_bfloat16 ha = __float2bfloat16_rn(a);
    __nv_bfloat16 hb = __float2bfloat16_rn(b);
    __nv_bfloat16 la = __float2bfloat16_rn(a - __bfloat162float(ha));
    __nv_bfloat16 lb = __float2bfloat16_rn(b - __bfloat162float(hb));
    hi = ((uint32_t)__bfloat16_as_ushort(hb) << 16) | __bfloat16_as_ushort(ha);
    lo = ((uint32_t)__bfloat16_as_ushort(lb) << 16) | __bfloat16_as_ushort(la);
}

__device__ __forceinline__ uint32_t packbf(float a, float b) {
    return ((uint32_t)__bfloat16_as_ushort(__float2bfloat16_rn(b)) << 16) |
           __bfloat16_as_ushort(__float2bfloat16_rn(a));
}

// Fast 2^x on the FMA pipe. Valid for x <= 0 (clamped at -126). |err|~2.4e-6.
__device__ __forceinline__ float fexp2(float x) {
    x = fmaxf(x, -126.0f);
    float n = rintf(x);
    float r = x - n;                       // exact, r in [-0.5, 0.5]
    float p = fmaf(r, 1.3333558e-3f, 9.6181291e-3f);
    p = fmaf(r, p, 5.5504109e-2f);
    p = fmaf(r, p, 2.4022651e-1f);
    p = fmaf(r, p, 6.9314718e-1f);
    p = fmaf(r, p, 1.0f);
    int e = ((int)n + 127) << 23;
    return p * __int_as_float(e);
}

// ---------------------------------------------------------------------------
// Prepass: fp32 -> bf16 hi/lo split for all 7 tensors in ONE launch.
// ---------------------------------------------------------------------------
__global__ __launch_bounds__(256) void conv_all(
    const float* __restrict__ q, const float* __restrict__ k,
    const float* __restrict__ v,
    const float* __restrict__ wq, const float* __restrict__ wk,
    const float* __restrict__ wv, const float* __restrict__ wo,
    __nv_bfloat16* qh, __nv_bfloat16* ql,
    __nv_bfloat16* kh, __nv_bfloat16* kl,
    __nv_bfloat16* vh, __nv_bfloat16* vl,
    __nv_bfloat16* wqh, __nv_bfloat16* wql,
    __nv_bfloat16* wkh, __nv_bfloat16* wkl,
    __nv_bfloat16* wvh, __nv_bfloat16* wvl,
    __nv_bfloat16* woh, __nv_bfloat16* wol)
{
    const int z = blockIdx.y;
    const float* src;
    __nv_bfloat16 *H, *L;
    int n4;
    switch (z) {
        case 0: src = q;  H = qh;  L = ql;  n4 = NELEM / 4; break;
        case 1: src = k;  H = kh;  L = kl;  n4 = NELEM / 4; break;
        case 2: src = v;  H = vh;  L = vl;  n4 = NELEM / 4; break;
        case 3: src = wq; H = wqh; L = wql; n4 = WELEM / 4; break;
        case 4: src = wk; H = wkh; L = wkl; n4 = WELEM / 4; break;
        case 5: src = wv; H = wvh; L = wvl; n4 = WELEM / 4; break;
        default: src = wo; H = woh; L = wol; n4 = WELEM / 4; break;
    }
    const int base = blockIdx.x * 1024 + threadIdx.x;
    if (base >= n4) return;
#pragma unroll
    for (int u = 0; u < 4; u++) {
        const int i = base + u * 256;
        if (i < n4) {
            float4 vv = ((const float4*)src)[i];
            uint2 h, l;
            split4(vv, h, l);
            ((uint2*)H)[i] = h;
            ((uint2*)L)[i] = l;
        }
    }
}

// ---------------------------------------------------------------------------
// bf16 HMMA GEMM body, 3-term split, cp.async 3-stage pipeline.
// Tile 128x128, BK=32, 256 threads, 8 warps 4(M)x2(N).
// MMA schedule: three passes of 16 INDEPENDENT MMAs (acc reuse distance 16)
// to cover HMMA latency -- the round-9 profile showed dependent 3-chains
// capping tensor at ~49%.
// ---------------------------------------------------------------------------
#define LDA_S   80
#define MAT_SZ  (128 * LDA_S)            // 10240
#define STG_SZ  (4 * MAT_SZ)             // 40960
#define GEMM_SMEM (3 * STG_SZ)           // 122880

struct GemmJob {
    const __nv_bfloat16 *Xh, *Xl, *Wh, *Wl;
    const float* bias;
    __nv_bfloat16 *Yh, *Yl;
    float oscale;
};

template <int MODE>
__device__ __forceinline__ void gemm_body(
    const __nv_bfloat16* __restrict__ Xh, const __nv_bfloat16* __restrict__ Xl,
    const __nv_bfloat16* __restrict__ Wh, const __nv_bfloat16* __restrict__ Wl,
    const float* __restrict__ bias,
    float* __restrict__ Yf,
    __nv_bfloat16* __restrict__ Yh, __nv_bfloat16* __restrict__ Yl,
    float oscale, char* sm)
{
    const uint32_t sb = smem_u32(sm);
    const int tid  = threadIdx.x;
    const int lane = tid & 31;
    const int wid  = tid >> 5;
    const int wm   = wid >> 1;
    const int wn   = wid & 1;

    const int m0 = blockIdx.x * 128;
    const int n0 = blockIdx.y * 128;
    const __nv_bfloat16* src[4] = {
        Xh + (size_t)m0 * Dn, Xl + (size_t)m0 * Dn,
        Wh + (size_t)n0 * Dn, Wl + (size_t)n0 * Dn };

    const int cr0 = (tid + 0)   >> 2;
    const int cc0 = (tid & 3)   * 16;
    const int cr1 = (tid + 256) >> 2;

    const uint32_t a_row = wm * 32 + (lane & 15);
    const uint32_t a_byt = (lane >> 4) * 16;
    const uint32_t b_row = wn * 64 + (lane & 7) + ((lane >> 4) << 3);
    const uint32_t b_byt = ((lane >> 3) & 1) * 16;

    float acc[2][8][4];
#pragma unroll
    for (int i = 0; i < 2; i++)
#pragma unroll
        for (int j = 0; j < 8; j++)
#pragma unroll
            for (int k = 0; k < 4; k++) acc[i][j][k] = 0.f;

    // prologue: stages 0,1
#pragma unroll
    for (int ps = 0; ps < 2; ps++) {
        const uint32_t st = sb + ps * STG_SZ;
#pragma unroll
        for (int mt = 0; mt < 4; mt++) {
            CP_ASYNC16(st + mt * MAT_SZ + cr0 * LDA_S + cc0,
                       src[mt] + (size_t)cr0 * Dn + ps * 32 + (cc0 >> 1));
            CP_ASYNC16(st + mt * MAT_SZ + cr1 * LDA_S + cc0,
                       src[mt] + (size_t)cr1 * Dn + ps * 32 + (cc0 >> 1));
        }
        CP_COMMIT();
    }

#pragma unroll 1
    for (int s = 0; s < 32; s++) {
        CP_WAIT1();
        __syncthreads();

        const uint32_t stg = sb + (s % 3) * STG_SZ;
#pragma unroll
        for (int ks = 0; ks < 2; ks++) {
            uint32_t ah[2][4], al[2][4], bh[4][4], bl[4][4];
#pragma unroll
            for (int mf = 0; mf < 2; mf++) {
                const uint32_t ao = stg + (a_row + mf * 16) * LDA_S + ks * 32 + a_byt;
                ldsm_x4(ah[mf], ao);
                ldsm_x4(al[mf], ao + MAT_SZ);
            }
#pragma unroll
            for (int nq = 0; nq < 4; nq++) {
                const uint32_t bo = stg + 2 * MAT_SZ +
                                    (b_row + nq * 16) * LDA_S + ks * 32 + b_byt;
                ldsm_x4(bh[nq], bo);
                ldsm_x4(bl[nq], bo + MAT_SZ);
            }
            // pass 1: Ah*Bh -- 16 independent MMAs
#pragma unroll
            for (int nq = 0; nq < 4; nq++)
#pragma unroll
                for (int mf = 0; mf < 2; mf++) {
                    mma16816(acc[mf][nq * 2 + 0], ah[mf], bh[nq][0], bh[nq][1]);
                    mma16816(acc[mf][nq * 2 + 1], ah[mf], bh[nq][2], bh[nq][3]);
                }
            // pass 2: Ah*Bl
#pragma unroll
            for (int nq = 0; nq < 4; nq++)
#pragma unroll
                for (int mf = 0; mf < 2; mf++) {
                    mma16816(acc[mf][nq * 2 + 0], ah[mf], bl[nq][0], bl[nq][1]);
                    mma16816(acc[mf][nq * 2 + 1], ah[mf], bl[nq][2], bl[nq][3]);
                }
            // pass 3: Al*Bh
#pragma unroll
            for (int nq = 0; nq < 4; nq++)
#pragma unroll
                for (int mf = 0; mf < 2; mf++) {
                    mma16816(acc[mf][nq * 2 + 0], al[mf], bh[nq][0], bh[nq][1]);
                    mma16816(acc[mf][nq * 2 + 1], al[mf], bh[nq][2], bh[nq][3]);
                }
        }

        if (s + 2 < 32) {
            const uint32_t st = sb + ((s + 2) % 3) * STG_SZ;
            const int k8 = (s + 2) * 32 + (cc0 >> 1);
#pragma unroll
            for (int mt = 0; mt < 4; mt++) {
                CP_ASYNC16(st + mt * MAT_SZ + cr0 * LDA_S + cc0,
                           src[mt] + (size_t)cr0 * Dn + k8);
                CP_ASYNC16(st + mt * MAT_SZ + cr1 * LDA_S + cc0,
                           src[mt] + (size_t)cr1 * Dn + k8);
            }
        }
        CP_COMMIT();
    }

#pragma unroll
    for (int mf = 0; mf < 2; mf++) {
        const int mr = m0 + wm * 32 + mf * 16 + (lane >> 2);
#pragma unroll
        for (int nf = 0; nf < 8; nf++) {
            const int c0 = n0 + wn * 64 + nf * 8 + (lane & 3) * 2;
            const float b0 = bias[c0], b1 = bias[c0 + 1];
#pragma unroll
            for (int rr = 0; rr < 2; rr++) {
                const int m = mr + rr * 8;
                float v0 = acc[mf][nf][rr * 2 + 0] + b0;
                float v1 = acc[mf][nf][rr * 2 + 1] + b1;
                if (MODE) {
                    v0 *= oscale; v1 *= oscale;
                    const int b = m >> 11, srow = m & (Sn - 1);
                    const int h = c0 >> 6, dk = c0 & 63;
                    const size_t idx =
                        (((size_t)(b * Hn + h)) * Sn + srow) * DKn + dk;
                    uint32_t hi, lo;
                    split2(v0, v1, hi, lo);
                    *(uint32_t*)(Yh + idx) = hi;
                    *(uint32_t*)(Yl + idx) = lo;
                } else {
                    float* dst = Yf + (size_t)m * Dn + c0;
                    dst[0] = v0; dst[1] = v1;
                }
            }
        }
    }
}

__global__ __launch_bounds__(256, 1) void gemm_proj(GemmJob a, GemmJob b, GemmJob c)
{
    extern __shared__ char sm[];
    GemmJob j = (blockIdx.z == 0) ? a : ((blockIdx.z == 1) ? b : c);
    gemm_body<1>(j.Xh, j.Xl, j.Wh, j.Wl, j.bias, nullptr, j.Yh, j.Yl,
                 j.oscale, sm);
}

__global__ __launch_bounds__(256, 1) void gemm_out(
    const __nv_bfloat16* Xh, const __nv_bfloat16* Xl,
    const __nv_bfloat16* Wh, const __nv_bfloat16* Wl,
    const float* bias, float* Yf)
{
    extern __shared__ char sm[];
    gemm_body<0>(Xh, Xl, Wh, Wl, bias, Yf, nullptr, nullptr, 1.0f, sm);
}

// ---------------------------------------------------------------------------
// HMMA causal flash attention (unchanged from round 9: 2 CTAs/SM, fexp2,
// cp.async double-buffered KV, Q pre-scaled into log2 domain).
// ---------------------------------------------------------------------------
#define LDS_B   144
#define QMAT    18432                  // 128 * 144
#define KVMAT   9216                   // 64 * 144
#define KV_STG  (4 * KVMAT)            // 36864: Kh,Kl,Vh,Vl
#define ATTN_SMEM (2 * KV_STG)         // 73728

__global__ __launch_bounds__(256, 2) void attn_tc()
{
    extern __shared__ char smem[];
    const uint32_t sb = smem_u32(smem);
    const int tid = threadIdx.x, lane = tid & 31, wid = tid >> 5;

    const int qt = 15 - blockIdx.x;       // heavy blocks first
    const int bh = blockIdx.y;
    const int q0 = qt * 128;

    const size_t base = (size_t)bh * Sn * DKn;
    const __nv_bfloat16* Qh = g_Qh + base;
    const __nv_bfloat16* Ql = g_Ql + base;
    const __nv_bfloat16* Kh = g_Kh + base;
    const __nv_bfloat16* Kl = g_Kl + base;
    const __nv_bfloat16* Vh = g_Vh + base;
    const __nv_bfloat16* Vl = g_Vl + base;

    // ---- stage Q (bf16 hi/lo) into buf1, then pull into A-frags ----
    {
        char* qhd = smem + KV_STG;
        char* qld = smem + KV_STG + QMAT;
#pragma unroll
        for (int i = 0; i < 4; i++) {
            const int c = tid + i * 256;
            const int row = c >> 3, ch = c & 7;
            const uint32_t off = row * LDS_B + ch * 16;
            *(uint4*)(qhd + off) =
                *(const uint4*)(Qh + (size_t)(q0 + row) * DKn + ch * 8);
            *(uint4*)(qld + off) =
                *(const uint4*)(Ql + (size_t)(q0 + row) * DKn + ch * 8);
        }
    }
    __syncthreads();

    uint32_t qfh[4][4], qfl[4][4];
    {
        const uint32_t arow = wid * 16 + (lane & 15);
        const uint32_t abyt = (lane >> 4) * 16;
#pragma unroll
        for (int kc = 0; kc < 4; kc++) {
            const uint32_t ao = sb + KV_STG + arow * LDS_B + kc * 32 + abyt;
            ldsm_x4(qfh[kc], ao);
            ldsm_x4(qfl[kc], ao + QMAT);
        }
    }

    float accO[8][4];
#pragma unroll
    for (int j = 0; j < 8; j++)
#pragma unroll
        for (int k = 0; k < 4; k++) accO[j][k] = 0.f;
    float m_lo = -1e30f, m_hi = -1e30f, l_lo = 0.f, l_hi = 0.f;

    const int r_lo = q0 + wid * 16 + (lane >> 2);
    const int r_hi = r_lo + 8;
    const uint32_t brow = (lane & 7) + ((lane >> 4) << 3);
    const uint32_t bbyt = ((lane >> 3) & 1) * 16;
    const uint32_t vbyt = (lane >> 4) * 16;

    const int ntiles = 2 * qt + 2;

    const int lr = tid >> 3;              // 0..31
    const int lc = (tid & 7) * 16;        // byte offset within row
    const int le = lc >> 1;               // bf16 element offset

    {
        const uint32_t st = sb;
#pragma unroll
        for (int rr = 0; rr < 2; rr++) {
            const int row = lr + rr * 32;
            const uint32_t so = row * LDS_B + lc;
            const size_t go = (size_t)row * DKn + le;
            CP_ASYNC16(st + 0 * KVMAT + so, Kh + go);
            CP_ASYNC16(st + 1 * KVMAT + so, Kl + go);
            CP_ASYNC16(st + 2 * KVMAT + so, Vh + go);
            CP_ASYNC16(st + 3 * KVMAT + so, Vl + go);
        }
        CP_COMMIT();
    }

#pragma unroll 1
    for (int kt = 0; kt < ntiles; kt++) {
        CP_WAIT0();
        __syncthreads();

        if (kt + 1 < ntiles) {
            const uint32_t st = sb + ((kt + 1) & 1) * KV_STG;
#pragma unroll
            for (int rr = 0; rr < 2; rr++) {
                const int row = lr + rr * 32;
                const uint32_t so = row * LDS_B + lc;
                const size_t go = (size_t)((kt + 1) * 64 + row) * DKn + le;
                CP_ASYNC16(st + 0 * KVMAT + so, Kh + go);
                CP_ASYNC16(st + 1 * KVMAT + so, Kl + go);
                CP_ASYNC16(st + 2 * KVMAT + so, Vh + go);
                CP_ASYNC16(st + 3 * KVMAT + so, Vl + go);
            }
        }
        CP_COMMIT();

        const uint32_t stg = sb + (kt & 1) * KV_STG;
        const int k0 = kt * 64;

        // ---- S = Q K^T (3-term), log2-domain scores ----
        float s[8][4];
#pragma unroll
        for (int j = 0; j < 8; j++)
#pragma unroll
            for (int k = 0; k < 4; k++) s[j][k] = 0.f;

#pragma unroll
        for (int kc = 0; kc < 4; kc++) {
#pragma unroll
            for (int nq = 0; nq < 4; nq++) {
                const uint32_t bo = stg + (brow + nq * 16) * LDS_B + kc * 32 + bbyt;
                uint32_t kh[4], kl[4];
                ldsm_x4(kh, bo);
                ldsm_x4(kl, bo + KVMAT);
                mma16816(s[nq * 2 + 0], qfh[kc], kh[0], kh[1]);
                mma16816(s[nq * 2 + 1], qfh[kc], kh[2], kh[3]);
                mma16816(s[nq * 2 + 0], qfh[kc], kl[0], kl[1]);
                mma16816(s[nq * 2 + 1], qfh[kc], kl[2], kl[3]);
                mma16816(s[nq * 2 + 0], qfl[kc], kh[0], kh[1]);
                mma16816(s[nq * 2 + 1], qfl[kc], kh[2], kh[3]);
            }
        }

        // ---- causal mask (scale already folded into Q) ----
        if ((k0 + 63) > r_lo) {
#pragma unroll
            for (int j = 0; j < 8; j++) {
                const int c = k0 + j * 8 + (lane & 3) * 2;
                if (c > r_lo)     s[j][0] = -1e30f;
                if (c + 1 > r_lo) s[j][1] = -1e30f;
                if (c > r_hi)     s[j][2] = -1e30f;
                if (c + 1 > r_hi) s[j][3] = -1e30f;
            }
        }

        // ---- online softmax (base-2) ----
        float mx0 = -1e30f, mx1 = -1e30f;
#pragma unroll
        for (int j = 0; j < 8; j++) {
            mx0 = fmaxf(mx0, fmaxf(s[j][0], s[j][1]));
            mx1 = fmaxf(mx1, fmaxf(s[j][2], s[j][3]));
        }
        mx0 = fmaxf(mx0, __shfl_xor_sync(0xffffffffu, mx0, 1));
        mx0 = fmaxf(mx0, __shfl_xor_sync(0xffffffffu, mx0, 2));
        mx1 = fmaxf(mx1, __shfl_xor_sync(0xffffffffu, mx1, 1));
        mx1 = fmaxf(mx1, __shfl_xor_sync(0xffffffffu, mx1, 2));
        const float mn0 = fmaxf(m_lo, mx0);
        const float mn1 = fmaxf(m_hi, mx1);
        const float a0 = fexp2(m_lo - mn0);
        const float a1 = fexp2(m_hi - mn1);
        m_lo = mn0; m_hi = mn1;

        float sum0 = 0.f, sum1 = 0.f;
#pragma unroll
        for (int j = 0; j < 8; j++) {
            s[j][0] = fexp2(s[j][0] - mn0);
            s[j][1] = fexp2(s[j][1] - mn0);
            s[j][2] = fexp2(s[j][2] - mn1);
            s[j][3] = fexp2(s[j][3] - mn1);
            sum0 += s[j][0] + s[j][1];
            sum1 += s[j][2] + s[j][3];
        }
        sum0 += __shfl_xor_sync(0xffffffffu, sum0, 1);
        sum0 += __shfl_xor_sync(0xffffffffu, sum0, 2);
        sum1 += __shfl_xor_sync(0xffffffffu, sum1, 1);
        sum1 += __shfl_xor_sync(0xffffffffu, sum1, 2);
        l_lo = l_lo * a0 + sum0;
        l_hi = l_hi * a1 + sum1;
#pragma unroll
        for (int j = 0; j < 8; j++) {
            accO[j][0] *= a0; accO[j][1] *= a0;
            accO[j][2] *= a1; accO[j][3] *= a1;
        }

        // ---- O += P V (3-term) ----
#pragma unroll
        for (int kc = 0; kc < 4; kc++) {
            uint32_t ph[4], pl[4];
            {
                const float p00 = s[2 * kc][0],     p01 = s[2 * kc][1];
                const float p02 = s[2 * kc][2],     p03 = s[2 * kc][3];
                const float p10 = s[2 * kc + 1][0], p11 = s[2 * kc + 1][1];
                const float p12 = s[2 * kc + 1][2], p13 = s[2 * kc + 1][3];
                ph[0] = packbf(p00, p01);
                ph[1] = packbf(p02, p03);
                ph[2] = packbf(p10, p11);
                ph[3] = packbf(p12, p13);
                pl[0] = packbf(p00 - __bfloat162float(__float2bfloat16_rn(p00)),
                               p01 - __bfloat162float(__float2bfloat16_rn(p01)));
                pl[1] = packbf(p02 - __bfloat162float(__float2bfloat16_rn(p02)),
                               p03 - __bfloat162float(__float2bfloat16_rn(p03)));
                pl[2] = packbf(p10 - __bfloat162float(__float2bfloat16_rn(p10)),
                               p11 - __bfloat162float(__float2bfloat16_rn(p11)));
                pl[3] = packbf(p12 - __bfloat162float(__float2bfloat16_rn(p12)),
                               p13 - __bfloat162float(__float2bfloat16_rn(p13)));
            }
            const uint32_t vrow = kc * 16 + (lane & 15);
#pragma unroll
            for (int np = 0; np < 4; np++) {
                const uint32_t vo = stg + 2 * KVMAT + vrow * LDS_B + np * 32 + vbyt;
                uint32_t vh[4], vl[4];
                ldsm_x4_t(vh, vo);
                ldsm_x4_t(vl, vo + KVMAT);
                mma16816(accO[np * 2 + 0], ph, vh[0], vh[1]);
                mma16816(accO[np * 2 + 1], ph, vh[2], vh[3]);
                mma16816(accO[np * 2 + 0], ph, vl[0], vl[1]);
                mma16816(accO[np * 2 + 1], ph, vl[2], vl[3]);
                mma16816(accO[np * 2 + 0], pl, vh[0], vh[1]);
                mma16816(accO[np * 2 + 1], pl, vh[2], vh[3]);
            }
        }
    }

    // ---- epilogue: normalize, split to bf16 hi/lo, write [B,S,D] ----
    const float il0 = 1.0f / l_lo;
    const float il1 = 1.0f / l_hi;
    const int b = bh >> 4, h = bh & 15;
    const int c_base = h * DKn + (lane & 3) * 2;
#pragma unroll
    for (int j = 0; j < 8; j++) {
        const int c = c_base + j * 8;
        const size_t i0 = ((size_t)(b * Sn + r_lo)) * Dn + c;
        const size_t i1 = ((size_t)(b * Sn + r_hi)) * Dn + c;
        uint32_t hi, lo;
        split2(accO[j][0] * il0, accO[j][1] * il0, hi, lo);
        *(uint32_t*)(g_Ah + i0) = hi;
        *(uint32_t*)(g_Al + i0) = lo;
        split2(accO[j][2] * il1, accO[j][3] * il1, hi, lo);
        *(uint32_t*)(g_Ah + i1) = hi;
        *(uint32_t*)(g_Al + i1) = lo;
    }
}

// ---------------------------------------------------------------------------
extern "C" void kernel_launch(void* const* d_in, const int* in_sizes, int n_in,
                              void* d_out, int out_size)
{
    const float* k_in = (const float*)d_in[0];
    const float* q_in = (const float*)d_in[1];
    const float* v_in = (const float*)d_in[2];
    const float* w_q  = (const float*)d_in[3];
    const float* b_q  = (const float*)d_in[4];
    const float* w_k  = (const float*)d_in[5];
    const float* b_k  = (const float*)d_in[6];
    const float* w_v  = (const float*)d_in[7];
    const float* b_v  = (const float*)d_in[8];
    const float* w_o  = (const float*)d_in[9];
    const float* b_o  = (const float*)d_in[10];
    float* out = (float*)d_out;

    __nv_bfloat16 *xqh, *xql, *xkh, *xkl, *xvh, *xvl;
    __nv_bfloat16 *wqh, *wql, *wkh, *wkl, *wvh, *wvl, *woh, *wol;
    __nv_bfloat16 *Qh, *Ql, *Kh, *Kl, *Vh, *Vl, *Ah, *Al;
    cudaGetSymbolAddress((void**)&xqh, g_xqh); cudaGetSymbolAddress((void**)&xql, g_xql);
    cudaGetSymbolAddress((void**)&xkh, g_xkh); cudaGetSymbolAddress((void**)&xkl, g_xkl);
    cudaGetSymbolAddress((void**)&xvh, g_xvh); cudaGetSymbolAddress((void**)&xvl, g_xvl);
    cudaGetSymbolAddress((void**)&wqh, g_wqh); cudaGetSymbolAddress((void**)&wql, g_wql);
    cudaGetSymbolAddress((void**)&wkh, g_wkh); cudaGetSymbolAddress((void**)&wkl, g_wkl);
    cudaGetSymbolAddress((void**)&wvh, g_wvh); cudaGetSymbolAddress((void**)&wvl, g_wvl);
    cudaGetSymbolAddress((void**)&woh, g_woh); cudaGetSymbolAddress((void**)&wol, g_wol);
    cudaGetSymbolAddress((void**)&Qh, g_Qh);   cudaGetSymbolAddress((void**)&Ql, g_Ql);
    cudaGetSymbolAddress((void**)&Kh, g_Kh);   cudaGetSymbolAddress((void**)&Kl, g_Kl);
    cudaGetSymbolAddress((void**)&Vh, g_Vh);   cudaGetSymbolAddress((void**)&Vl, g_Vl);
    cudaGetSymbolAddress((void**)&Ah, g_Ah);   cudaGetSymbolAddress((void**)&Al, g_Al);

    cudaFuncSetAttribute(gemm_proj, cudaFuncAttributeMaxDynamicSharedMemorySize,
                         GEMM_SMEM);
    cudaFuncSetAttribute(gemm_out, cudaFuncAttributeMaxDynamicSharedMemorySize,
                         GEMM_SMEM);
    cudaFuncSetAttribute(attn_tc, cudaFuncAttributeMaxDynamicSharedMemorySize,
                         ATTN_SMEM);

    // one-launch conversion prepass
    conv_all<<<dim3(1024, 7), 256>>>(
        q_in, k_in, v_in, w_q, w_k, w_v, w_o,
        xqh, xql, xkh, xkl, xvh, xvl,
        wqh, wql, wkh, wkl, wvh, wvl, woh, wol);

    // merged Q/K/V projection GEMMs (Q output pre-scaled by 0.125*log2e)
    GemmJob jq = { xqh, xql, wqh, wql, b_q, Qh, Ql, 0.125f * 1.4426950408889634f };
    GemmJob jk = { xkh, xkl, wkh, wkl, b_k, Kh, Kl, 1.0f };
    GemmJob jv = { xvh, xvl, wvh, wvl, b_v, Vh, Vl, 1.0f };
    gemm_proj<<<dim3(32, 8, 3), 256, GEMM_SMEM>>>(jq, jk, jv);

    attn_tc<<<dim3(16, 32), 256, ATTN_SMEM>>>();

    gemm_out<<<dim3(32, 8), 256, GEMM_SMEM>>>(Ah, Al, woh, wol, b_o, out);
}

// round 11
// speedup vs baseline: 1.0265x; 1.0265x over previous
#include <cuda_runtime.h>
#include <cuda_bf16.h>
#include <cstdint>

#define Bn 2
#define Sn 2048
#define Dn 1024
#define Hn 16
#define DKn 64

#define NELEM (4096 * 1024)
#define WELEM (1024 * 1024)

// bf16 hi/lo scratch (device globals; no allocations allowed)
__device__ __nv_bfloat16 g_xqh[NELEM], g_xql[NELEM];
__device__ __nv_bfloat16 g_xkh[NELEM], g_xkl[NELEM];
__device__ __nv_bfloat16 g_xvh[NELEM], g_xvl[NELEM];
__device__ __nv_bfloat16 g_wqh[WELEM], g_wql[WELEM];
__device__ __nv_bfloat16 g_wkh[WELEM], g_wkl[WELEM];
__device__ __nv_bfloat16 g_wvh[WELEM], g_wvl[WELEM];
__device__ __nv_bfloat16 g_woh[WELEM], g_wol[WELEM];
__device__ __nv_bfloat16 g_Qh[NELEM], g_Ql[NELEM];   // [B,H,S,DK] (pre-scaled)
__device__ __nv_bfloat16 g_Kh[NELEM], g_Kl[NELEM];
__device__ __nv_bfloat16 g_Vh[NELEM], g_Vl[NELEM];
__device__ __nv_bfloat16 g_Ah[NELEM], g_Al[NELEM];   // [B,S,D]

// ---------------------------------------------------------------------------
// Helpers
// ---------------------------------------------------------------------------
__device__ __forceinline__ uint32_t smem_u32(const void* p) {
    uint32_t a;
    asm("{ .reg .u64 t; cvta.to.shared.u64 t, %1; cvt.u32.u64 %0, t; }"
        : "=r"(a) : "l"(p));
    return a;
}

__device__ __forceinline__ void ldsm_x4(uint32_t (&r)[4], uint32_t addr) {
    asm volatile("ldmatrix.sync.aligned.m8n8.x4.shared.b16 {%0,%1,%2,%3}, [%4];"
        : "=r"(r[0]), "=r"(r[1]), "=r"(r[2]), "=r"(r[3]) : "r"(addr));
}

__device__ __forceinline__ void ldsm_x4_t(uint32_t (&r)[4], uint32_t addr) {
    asm volatile("ldmatrix.sync.aligned.m8n8.x4.trans.shared.b16 {%0,%1,%2,%3}, [%4];"
        : "=r"(r[0]), "=r"(r[1]), "=r"(r[2]), "=r"(r[3]) : "r"(addr));
}

__device__ __forceinline__ void mma16816(float (&d)[4], const uint32_t (&a)[4],
                                         uint32_t b0, uint32_t b1) {
    asm volatile(
        "mma.sync.aligned.m16n8k16.row.col.f32.bf16.bf16.f32 "
        "{%0,%1,%2,%3}, {%4,%5,%6,%7}, {%8,%9}, {%0,%1,%2,%3};"
        : "+f"(d[0]), "+f"(d[1]), "+f"(d[2]), "+f"(d[3])
        : "r"(a[0]), "r"(a[1]), "r"(a[2]), "r"(a[3]), "r"(b0), "r"(b1));
}

#define CP_ASYNC16(dst, src) \
    asm volatile("cp.async.cg.shared.global [%0], [%1], 16;" \
                 :: "r"(dst), "l"(src) : "memory")
#define CP_COMMIT()  asm volatile("cp.async.commit_group;" ::: "memory")
#define CP_WAIT0()   asm volatile("cp.async.wait_group 0;" ::: "memory")
#define CP_WAIT1()   asm volatile("cp.async.wait_group 1;" ::: "memory")

__device__ __forceinline__ void split4(float4 v, uint2& hi, uint2& lo) {
    __nv_bfloat16 h0 = __float2bfloat16_rn(v.x);
    __nv_bfloat16 h1 = __float2bfloat16_rn(v.y);
    __nv_bfloat16 h2 = __float2bfloat16_rn(v.z);
    __nv_bfloat16 h3 = __float2bfloat16_rn(v.w);
    __nv_bfloat16 l0 = __float2bfloat16_rn(v.x - __bfloat162float(h0));
    __nv_bfloat16 l1 = __float2bfloat16_rn(v.y - __bfloat162float(h1));
    __nv_bfloat16 l2 = __float2bfloat16_rn(v.z - __bfloat162float(h2));
    __nv_bfloat16 l3 = __float2bfloat16_rn(v.w - __bfloat162float(h3));
    hi.x = ((uint32_t)__bfloat16_as_ushort(h1) << 16) | __bfloat16_as_ushort(h0);
    hi.y = ((uint32_t)__bfloat16_as_ushort(h3) << 16) | __bfloat16_as_ushort(h2);
    lo.x = ((uint32_t)__bfloat16_as_ushort(l1) << 16) | __bfloat16_as_ushort(l0);
    lo.y = ((uint32_t)__bfloat16_as_ushort(l3) << 16) | __bfloat16_as_ushort(l2);
}

__device__ __forceinline__ void split2(float a, float b, uint32_t& hi, uint32_t& lo) {
    __nv_bfloat16 ha = __float2bfloat16_rn(a);
    __nv_bfloat16 hb = __float2bfloat16_rn(b);
    __nv_bfloat16 la = __float2bfloat16_rn(a - __bfloat162float(ha));
    __nv_bfloat16 lb = __float2bfloat16_rn(b - __bfloat162float(hb));
    hi = ((uint32_t)__bfloat16_as_ushort(hb) << 16) | __bfloat16_as_ushort(ha);
    lo = ((uint32_t)__bfloat16_as_ushort(lb) << 16) | __bfloat16_as_ushort(la);
}

__device__ __forceinline__ uint32_t packbf(float a, float b) {
    return ((uint32_t)__bfloat16_as_ushort(__float2bfloat16_rn(b)) << 16) |
           __bfloat16_as_ushort(__float2bfloat16_rn(a));
}

// Fast 2^x on the FMA pipe. Valid for x <= 0 (clamped at -126). |err|~2.4e-6.
__device__ __forceinline__ float fexp2(float x) {
    x = fmaxf(x, -126.0f);
    float n = rintf(x);
    float r = x - n;                       // exact, r in [-0.5, 0.5]
    float p = fmaf(r, 1.3333558e-3f, 9.6181291e-3f);
    p = fmaf(r, p, 5.5504109e-2f);
    p = fmaf(r, p, 2.4022651e-1f);
    p = fmaf(r, p, 6.9314718e-1f);
    p = fmaf(r, p, 1.0f);
    int e = ((int)n + 127) << 23;
    return p * __int_as_float(e);
}

// ---------------------------------------------------------------------------
// Prepass: fp32 -> bf16 hi/lo split for all 7 tensors in ONE launch.
// ---------------------------------------------------------------------------
__global__ __launch_bounds__(256) void conv_all(
    const float* __restrict__ q, const float* __restrict__ k,
    const float* __restrict__ v,
    const float* __restrict__ wq, const float* __restrict__ wk,
    const float* __restrict__ wv, const float* __restrict__ wo,
    __nv_bfloat16* qh, __nv_bfloat16* ql,
    __nv_bfloat16* kh, __nv_bfloat16* kl,
    __nv_bfloat16* vh, __nv_bfloat16* vl,
    __nv_bfloat16* wqh, __nv_bfloat16* wql,
    __nv_bfloat16* wkh, __nv_bfloat16* wkl,
    __nv_bfloat16* wvh, __nv_bfloat16* wvl,
    __nv_bfloat16* woh, __nv_bfloat16* wol)
{
    const int z = blockIdx.y;
    const float* src;
    __nv_bfloat16 *H, *L;
    int n4;
    switch (z) {
        case 0: src = q;  H = qh;  L = ql;  n4 = NELEM / 4; break;
        case 1: src = k;  H = kh;  L = kl;  n4 = NELEM / 4; break;
        case 2: src = v;  H = vh;  L = vl;  n4 = NELEM / 4; break;
        case 3: src = wq; H = wqh; L = wql; n4 = WELEM / 4; break;
        case 4: src = wk; H = wkh; L = wkl; n4 = WELEM / 4; break;
        case 5: src = wv; H = wvh; L = wvl; n4 = WELEM / 4; break;
        default: src = wo; H = woh; L = wol; n4 = WELEM / 4; break;
    }
    const int base = blockIdx.x * 1024 + threadIdx.x;
    if (base >= n4) return;
#pragma unroll
    for (int u = 0; u < 4; u++) {
        const int i = base + u * 256;
        if (i < n4) {
            float4 vv = ((const float4*)src)[i];
            uint2 h, l;
            split4(vv, h, l);
            ((uint2*)H)[i] = h;
            ((uint2*)L)[i] = l;
        }
    }
}

// ---------------------------------------------------------------------------
// bf16 HMMA GEMM body, 3-term split, cp.async 2-stage pipeline, 2 CTAs/SM,
// with an INDEPENDENT 3-pass MMA schedule over nq-pairs (acc reuse dist 8).
// Tile 128x128, BK=32, 256 threads, 8 warps 4(M)x2(N).
// ---------------------------------------------------------------------------
#define LDA_S   80
#define MAT_SZ  (128 * LDA_S)            // 10240
#define STG_SZ  (4 * MAT_SZ)             // 40960
#define GEMM_SMEM (2 * STG_SZ)           // 81920

struct GemmJob {
    const __nv_bfloat16 *Xh, *Xl, *Wh, *Wl;
    const float* bias;
    __nv_bfloat16 *Yh, *Yl;
    float oscale;
};

template <int MODE>
__device__ __forceinline__ void gemm_body(
    const __nv_bfloat16* __restrict__ Xh, const __nv_bfloat16* __restrict__ Xl,
    const __nv_bfloat16* __restrict__ Wh, const __nv_bfloat16* __restrict__ Wl,
    const float* __restrict__ bias,
    float* __restrict__ Yf,
    __nv_bfloat16* __restrict__ Yh, __nv_bfloat16* __restrict__ Yl,
    float oscale, char* sm)
{
    const uint32_t sb = smem_u32(sm);
    const int tid  = threadIdx.x;
    const int lane = tid & 31;
    const int wid  = tid >> 5;
    const int wm   = wid >> 1;
    const int wn   = wid & 1;

    const int m0 = blockIdx.x * 128;
    const int n0 = blockIdx.y * 128;
    const __nv_bfloat16* src[4] = {
        Xh + (size_t)m0 * Dn, Xl + (size_t)m0 * Dn,
        Wh + (size_t)n0 * Dn, Wl + (size_t)n0 * Dn };

    const int cr0 = (tid + 0)   >> 2;
    const int cc0 = (tid & 3)   * 16;
    const int cr1 = (tid + 256) >> 2;

    const uint32_t a_row = wm * 32 + (lane & 15);
    const uint32_t a_byt = (lane >> 4) * 16;
    const uint32_t b_row = wn * 64 + (lane & 7) + ((lane >> 4) << 3);
    const uint32_t b_byt = ((lane >> 3) & 1) * 16;

    float acc[2][8][4];
#pragma unroll
    for (int i = 0; i < 2; i++)
#pragma unroll
        for (int j = 0; j < 8; j++)
#pragma unroll
            for (int k = 0; k < 4; k++) acc[i][j][k] = 0.f;

    // prologue: stages 0,1
#pragma unroll
    for (int ps = 0; ps < 2; ps++) {
        const uint32_t st = sb + ps * STG_SZ;
#pragma unroll
        for (int mt = 0; mt < 4; mt++) {
            CP_ASYNC16(st + mt * MAT_SZ + cr0 * LDA_S + cc0,
                       src[mt] + (size_t)cr0 * Dn + ps * 32 + (cc0 >> 1));
            CP_ASYNC16(st + mt * MAT_SZ + cr1 * LDA_S + cc0,
                       src[mt] + (size_t)cr1 * Dn + ps * 32 + (cc0 >> 1));
        }
        CP_COMMIT();
    }

#pragma unroll 1
    for (int s = 0; s < 32; s++) {
        CP_WAIT1();               // stage s resident (s+1 may be in flight)
        __syncthreads();

        const uint32_t stg = sb + (s & 1) * STG_SZ;
#pragma unroll
        for (int ks = 0; ks < 2; ks++) {
            uint32_t ah[2][4], al[2][4];
#pragma unroll
            for (int mf = 0; mf < 2; mf++) {
                const uint32_t ao = stg + (a_row + mf * 16) * LDA_S + ks * 32 + a_byt;
                ldsm_x4(ah[mf], ao);
                ldsm_x4(al[mf], ao + MAT_SZ);
            }
#pragma unroll
            for (int half = 0; half < 2; half++) {
                uint32_t bh[2][4], bl[2][4];
#pragma unroll
                for (int p = 0; p < 2; p++) {
                    const int nq = half * 2 + p;
                    const uint32_t bo = stg + 2 * MAT_SZ +
                                        (b_row + nq * 16) * LDA_S + ks * 32 + b_byt;
                    ldsm_x4(bh[p], bo);
                    ldsm_x4(bl[p], bo + MAT_SZ);
                }
                // pass 1: Ah*Bh -- 8 independent MMAs
#pragma unroll
                for (int p = 0; p < 2; p++)
#pragma unroll
                    for (int mf = 0; mf < 2; mf++) {
                        const int nq = half * 2 + p;
                        mma16816(acc[mf][nq * 2 + 0], ah[mf], bh[p][0], bh[p][1]);
                        mma16816(acc[mf][nq * 2 + 1], ah[mf], bh[p][2], bh[p][3]);
                    }
                // pass 2: Ah*Bl
#pragma unroll
                for (int p = 0; p < 2; p++)
#pragma unroll
                    for (int mf = 0; mf < 2; mf++) {
                        const int nq = half * 2 + p;
                        mma16816(acc[mf][nq * 2 + 0], ah[mf], bl[p][0], bl[p][1]);
                        mma16816(acc[mf][nq * 2 + 1], ah[mf], bl[p][2], bl[p][3]);
                    }
                // pass 3: Al*Bh
#pragma unroll
                for (int p = 0; p < 2; p++)
#pragma unroll
                    for (int mf = 0; mf < 2; mf++) {
                        const int nq = half * 2 + p;
                        mma16816(acc[mf][nq * 2 + 0], al[mf], bh[p][0], bh[p][1]);
                        mma16816(acc[mf][nq * 2 + 1], al[mf], bh[p][2], bh[p][3]);
                    }
            }
        }

        __syncthreads();          // all warps done reading buf s&1
        if (s + 2 < 32) {
            const uint32_t st = sb + (s & 1) * STG_SZ;   // reuse just-freed buf
            const int k8 = (s + 2) * 32 + (cc0 >> 1);
#pragma unroll
            for (int mt = 0; mt < 4; mt++) {
                CP_ASYNC16(st + mt * MAT_SZ + cr0 * LDA_S + cc0,
                           src[mt] + (size_t)cr0 * Dn + k8);
                CP_ASYNC16(st + mt * MAT_SZ + cr1 * LDA_S + cc0,
                           src[mt] + (size_t)cr1 * Dn + k8);
            }
        }
        CP_COMMIT();
    }

#pragma unroll
    for (int mf = 0; mf < 2; mf++) {
        const int mr = m0 + wm * 32 + mf * 16 + (lane >> 2);
#pragma unroll
        for (int nf = 0; nf < 8; nf++) {
            const int c0 = n0 + wn * 64 + nf * 8 + (lane & 3) * 2;
            const float b0 = bias[c0], b1 = bias[c0 + 1];
#pragma unroll
            for (int rr = 0; rr < 2; rr++) {
                const int m = mr + rr * 8;
                float v0 = acc[mf][nf][rr * 2 + 0] + b0;
                float v1 = acc[mf][nf][rr * 2 + 1] + b1;
                if (MODE) {
                    v0 *= oscale; v1 *= oscale;
                    const int b = m >> 11, srow = m & (Sn - 1);
                    const int h = c0 >> 6, dk = c0 & 63;
                    const size_t idx =
                        (((size_t)(b * Hn + h)) * Sn + srow) * DKn + dk;
                    uint32_t hi, lo;
                    split2(v0, v1, hi, lo);
                    *(uint32_t*)(Yh + idx) = hi;
                    *(uint32_t*)(Yl + idx) = lo;
                } else {
                    float* dst = Yf + (size_t)m * Dn + c0;
                    dst[0] = v0; dst[1] = v1;
                }
            }
        }
    }
}

__global__ __launch_bounds__(256, 2) void gemm_proj(GemmJob a, GemmJob b, GemmJob c)
{
    extern __shared__ char sm[];
    GemmJob j = (blockIdx.z == 0) ? a : ((blockIdx.z == 1) ? b : c);
    gemm_body<1>(j.Xh, j.Xl, j.Wh, j.Wl, j.bias, nullptr, j.Yh, j.Yl,
                 j.oscale, sm);
}

__global__ __launch_bounds__(256, 2) void gemm_out(
    const __nv_bfloat16* Xh, const __nv_bfloat16* Xl,
    const __nv_bfloat16* Wh, const __nv_bfloat16* Wl,
    const float* bias, float* Yf)
{
    extern __shared__ char sm[];
    gemm_body<0>(Xh, Xl, Wh, Wl, bias, Yf, nullptr, nullptr, 1.0f, sm);
}

// ---------------------------------------------------------------------------
// HMMA causal flash attention (unchanged from round 9: 2 CTAs/SM, fexp2,
// cp.async double-buffered KV, Q pre-scaled into log2 domain).
// ---------------------------------------------------------------------------
#define LDS_B   144
#define QMAT    18432                  // 128 * 144
#define KVMAT   9216                   // 64 * 144
#define KV_STG  (4 * KVMAT)            // 36864: Kh,Kl,Vh,Vl
#define ATTN_SMEM (2 * KV_STG)         // 73728

__global__ __launch_bounds__(256, 2) void attn_tc()
{
    extern __shared__ char smem[];
    const uint32_t sb = smem_u32(smem);
    const int tid = threadIdx.x, lane = tid & 31, wid = tid >> 5;

    const int qt = 15 - blockIdx.x;       // heavy blocks first
    const int bh = blockIdx.y;
    const int q0 = qt * 128;

    const size_t base = (size_t)bh * Sn * DKn;
    const __nv_bfloat16* Qh = g_Qh + base;
    const __nv_bfloat16* Ql = g_Ql + base;
    const __nv_bfloat16* Kh = g_Kh + base;
    const __nv_bfloat16* Kl = g_Kl + base;
    const __nv_bfloat16* Vh = g_Vh + base;
    const __nv_bfloat16* Vl = g_Vl + base;

    // ---- stage Q (bf16 hi/lo) into buf1, then pull into A-frags ----
    {
        char* qhd = smem + KV_STG;
        char* qld = smem + KV_STG + QMAT;
#pragma unroll
        for (int i = 0; i < 4; i++) {
            const int c = tid + i * 256;
            const int row = c >> 3, ch = c & 7;
            const uint32_t off = row * LDS_B + ch * 16;
            *(uint4*)(qhd + off) =
                *(const uint4*)(Qh + (size_t)(q0 + row) * DKn + ch * 8);
            *(uint4*)(qld + off) =
                *(const uint4*)(Ql + (size_t)(q0 + row) * DKn + ch * 8);
        }
    }
    __syncthreads();

    uint32_t qfh[4][4], qfl[4][4];
    {
        const uint32_t arow = wid * 16 + (lane & 15);
        const uint32_t abyt = (lane >> 4) * 16;
#pragma unroll
        for (int kc = 0; kc < 4; kc++) {
            const uint32_t ao = sb + KV_STG + arow * LDS_B + kc * 32 + abyt;
            ldsm_x4(qfh[kc], ao);
            ldsm_x4(qfl[kc], ao + QMAT);
        }
    }

    float accO[8][4];
#pragma unroll
    for (int j = 0; j < 8; j++)
#pragma unroll
        for (int k = 0; k < 4; k++) accO[j][k] = 0.f;
    float m_lo = -1e30f, m_hi = -1e30f, l_lo = 0.f, l_hi = 0.f;

    const int r_lo = q0 + wid * 16 + (lane >> 2);
    const int r_hi = r_lo + 8;
    const uint32_t brow = (lane & 7) + ((lane >> 4) << 3);
    const uint32_t bbyt = ((lane >> 3) & 1) * 16;
    const uint32_t vbyt = (lane >> 4) * 16;

    const int ntiles = 2 * qt + 2;

    const int lr = tid >> 3;              // 0..31
    const int lc = (tid & 7) * 16;        // byte offset within row
    const int le = lc >> 1;               // bf16 element offset

    {
        const uint32_t st = sb;
#pragma unroll
        for (int rr = 0; rr < 2; rr++) {
            const int row = lr + rr * 32;
            const uint32_t so = row * LDS_B + lc;
            const size_t go = (size_t)row * DKn + le;
            CP_ASYNC16(st + 0 * KVMAT + so, Kh + go);
            CP_ASYNC16(st + 1 * KVMAT + so, Kl + go);
            CP_ASYNC16(st + 2 * KVMAT + so, Vh + go);
            CP_ASYNC16(st + 3 * KVMAT + so, Vl + go);
        }
        CP_COMMIT();
    }

#pragma unroll 1
    for (int kt = 0; kt < ntiles; kt++) {
        CP_WAIT0();
        __syncthreads();

        if (kt + 1 < ntiles) {
            const uint32_t st = sb + ((kt + 1) & 1) * KV_STG;
#pragma unroll
            for (int rr = 0; rr < 2; rr++) {
                const int row = lr + rr * 32;
                const uint32_t so = row * LDS_B + lc;
                const size_t go = (size_t)((kt + 1) * 64 + row) * DKn + le;
                CP_ASYNC16(st + 0 * KVMAT + so, Kh + go);
                CP_ASYNC16(st + 1 * KVMAT + so, Kl + go);
                CP_ASYNC16(st + 2 * KVMAT + so, Vh + go);
                CP_ASYNC16(st + 3 * KVMAT + so, Vl + go);
            }
        }
        CP_COMMIT();

        const uint32_t stg = sb + (kt & 1) * KV_STG;
        const int k0 = kt * 64;

        // ---- S = Q K^T (3-term), log2-domain scores ----
        float s[8][4];
#pragma unroll
        for (int j = 0; j < 8; j++)
#pragma unroll
            for (int k = 0; k < 4; k++) s[j][k] = 0.f;

#pragma unroll
        for (int kc = 0; kc < 4; kc++) {
#pragma unroll
            for (int nq = 0; nq < 4; nq++) {
                const uint32_t bo = stg + (brow + nq * 16) * LDS_B + kc * 32 + bbyt;
                uint32_t kh[4], kl[4];
                ldsm_x4(kh, bo);
                ldsm_x4(kl, bo + KVMAT);
                mma16816(s[nq * 2 + 0], qfh[kc], kh[0], kh[1]);
                mma16816(s[nq * 2 + 1], qfh[kc], kh[2], kh[3]);
                mma16816(s[nq * 2 + 0], qfh[kc], kl[0], kl[1]);
                mma16816(s[nq * 2 + 1], qfh[kc], kl[2], kl[3]);
                mma16816(s[nq * 2 + 0], qfl[kc], kh[0], kh[1]);
                mma16816(s[nq * 2 + 1], qfl[kc], kh[2], kh[3]);
            }
        }

        // ---- causal mask (scale already folded into Q) ----
        if ((k0 + 63) > r_lo) {
#pragma unroll
            for (int j = 0; j < 8; j++) {
                const int c = k0 + j * 8 + (lane & 3) * 2;
                if (c > r_lo)     s[j][0] = -1e30f;
                if (c + 1 > r_lo) s[j][1] = -1e30f;
                if (c > r_hi)     s[j][2] = -1e30f;
                if (c + 1 > r_hi) s[j][3] = -1e30f;
            }
        }

        // ---- online softmax (base-2) ----
        float mx0 = -1e30f, mx1 = -1e30f;
#pragma unroll
        for (int j = 0; j < 8; j++) {
            mx0 = fmaxf(mx0, fmaxf(s[j][0], s[j][1]));
            mx1 = fmaxf(mx1, fmaxf(s[j][2], s[j][3]));
        }
        mx0 = fmaxf(mx0, __shfl_xor_sync(0xffffffffu, mx0, 1));
        mx0 = fmaxf(mx0, __shfl_xor_sync(0xffffffffu, mx0, 2));
        mx1 = fmaxf(mx1, __shfl_xor_sync(0xffffffffu, mx1, 1));
        mx1 = fmaxf(mx1, __shfl_xor_sync(0xffffffffu, mx1, 2));
        const float mn0 = fmaxf(m_lo, mx0);
        const float mn1 = fmaxf(m_hi, mx1);
        const float a0 = fexp2(m_lo - mn0);
        const float a1 = fexp2(m_hi - mn1);
        m_lo = mn0; m_hi = mn1;

        float sum0 = 0.f, sum1 = 0.f;
#pragma unroll
        for (int j = 0; j < 8; j++) {
            s[j][0] = fexp2(s[j][0] - mn0);
            s[j][1] = fexp2(s[j][1] - mn0);
            s[j][2] = fexp2(s[j][2] - mn1);
            s[j][3] = fexp2(s[j][3] - mn1);
            sum0 += s[j][0] + s[j][1];
            sum1 += s[j][2] + s[j][3];
        }
        sum0 += __shfl_xor_sync(0xffffffffu, sum0, 1);
        sum0 += __shfl_xor_sync(0xffffffffu, sum0, 2);
        sum1 += __shfl_xor_sync(0xffffffffu, sum1, 1);
        sum1 += __shfl_xor_sync(0xffffffffu, sum1, 2);
        l_lo = l_lo * a0 + sum0;
        l_hi = l_hi * a1 + sum1;
#pragma unroll
        for (int j = 0; j < 8; j++) {
            accO[j][0] *= a0; accO[j][1] *= a0;
            accO[j][2] *= a1; accO[j][3] *= a1;
        }

        // ---- O += P V (3-term) ----
#pragma unroll
        for (int kc = 0; kc < 4; kc++) {
            uint32_t ph[4], pl[4];
            {
                const float p00 = s[2 * kc][0],     p01 = s[2 * kc][1];
                const float p02 = s[2 * kc][2],     p03 = s[2 * kc][3];
                const float p10 = s[2 * kc + 1][0], p11 = s[2 * kc + 1][1];
                const float p12 = s[2 * kc + 1][2], p13 = s[2 * kc + 1][3];
                ph[0] = packbf(p00, p01);
                ph[1] = packbf(p02, p03);
                ph[2] = packbf(p10, p11);
                ph[3] = packbf(p12, p13);
                pl[0] = packbf(p00 - __bfloat162float(__float2bfloat16_rn(p00)),
                               p01 - __bfloat162float(__float2bfloat16_rn(p01)));
                pl[1] = packbf(p02 - __bfloat162float(__float2bfloat16_rn(p02)),
                               p03 - __bfloat162float(__float2bfloat16_rn(p03)));
                pl[2] = packbf(p10 - __bfloat162float(__float2bfloat16_rn(p10)),
                               p11 - __bfloat162float(__float2bfloat16_rn(p11)));
                pl[3] = packbf(p12 - __bfloat162float(__float2bfloat16_rn(p12)),
                               p13 - __bfloat162float(__float2bfloat16_rn(p13)));
            }
            const uint32_t vrow = kc * 16 + (lane & 15);
#pragma unroll
            for (int np = 0; np < 4; np++) {
                const uint32_t vo = stg + 2 * KVMAT + vrow * LDS_B + np * 32 + vbyt;
                uint32_t vh[4], vl[4];
                ldsm_x4_t(vh, vo);
                ldsm_x4_t(vl, vo + KVMAT);
                mma16816(accO[np * 2 + 0], ph, vh[0], vh[1]);
                mma16816(accO[np * 2 + 1], ph, vh[2], vh[3]);
                mma16816(accO[np * 2 + 0], ph, vl[0], vl[1]);
                mma16816(accO[np * 2 + 1], ph, vl[2], vl[3]);
                mma16816(accO[np * 2 + 0], pl, vh[0], vh[1]);
                mma16816(accO[np * 2 + 1], pl, vh[2], vh[3]);
            }
        }
    }

    // ---- epilogue: normalize, split to bf16 hi/lo, write [B,S,D] ----
    const float il0 = 1.0f / l_lo;
    const float il1 = 1.0f / l_hi;
    const int b = bh >> 4, h = bh & 15;
    const int c_base = h * DKn + (lane & 3) * 2;
#pragma unroll
    for (int j = 0; j < 8; j++) {
        const int c = c_base + j * 8;
        const size_t i0 = ((size_t)(b * Sn + r_lo)) * Dn + c;
        const size_t i1 = ((size_t)(b * Sn + r_hi)) * Dn + c;
        uint32_t hi, lo;
        split2(accO[j][0] * il0, accO[j][1] * il0, hi, lo);
        *(uint32_t*)(g_Ah + i0) = hi;
        *(uint32_t*)(g_Al + i0) = lo;
        split2(accO[j][2] * il1, accO[j][3] * il1, hi, lo);
        *(uint32_t*)(g_Ah + i1) = hi;
        *(uint32_t*)(g_Al + i1) = lo;
    }
}

// ---------------------------------------------------------------------------
extern "C" void kernel_launch(void* const* d_in, const int* in_sizes, int n_in,
                              void* d_out, int out_size)
{
    const float* k_in = (const float*)d_in[0];
    const float* q_in = (const float*)d_in[1];
    const float* v_in = (const float*)d_in[2];
    const float* w_q  = (const float*)d_in[3];
    const float* b_q  = (const float*)d_in[4];
    const float* w_k  = (const float*)d_in[5];
    const float* b_k  = (const float*)d_in[6];
    const float* w_v  = (const float*)d_in[7];
    const float* b_v  = (const float*)d_in[8];
    const float* w_o  = (const float*)d_in[9];
    const float* b_o  = (const float*)d_in[10];
    float* out = (float*)d_out;

    __nv_bfloat16 *xqh, *xql, *xkh, *xkl, *xvh, *xvl;
    __nv_bfloat16 *wqh, *wql, *wkh, *wkl, *wvh, *wvl, *woh, *wol;
    __nv_bfloat16 *Qh, *Ql, *Kh, *Kl, *Vh, *Vl, *Ah, *Al;
    cudaGetSymbolAddress((void**)&xqh, g_xqh); cudaGetSymbolAddress((void**)&xql, g_xql);
    cudaGetSymbolAddress((void**)&xkh, g_xkh); cudaGetSymbolAddress((void**)&xkl, g_xkl);
    cudaGetSymbolAddress((void**)&xvh, g_xvh); cudaGetSymbolAddress((void**)&xvl, g_xvl);
    cudaGetSymbolAddress((void**)&wqh, g_wqh); cudaGetSymbolAddress((void**)&wql, g_wql);
    cudaGetSymbolAddress((void**)&wkh, g_wkh); cudaGetSymbolAddress((void**)&wkl, g_wkl);
    cudaGetSymbolAddress((void**)&wvh, g_wvh); cudaGetSymbolAddress((void**)&wvl, g_wvl);
    cudaGetSymbolAddress((void**)&woh, g_woh); cudaGetSymbolAddress((void**)&wol, g_wol);
    cudaGetSymbolAddress((void**)&Qh, g_Qh);   cudaGetSymbolAddress((void**)&Ql, g_Ql);
    cudaGetSymbolAddress((void**)&Kh, g_Kh);   cudaGetSymbolAddress((void**)&Kl, g_Kl);
    cudaGetSymbolAddress((void**)&Vh, g_Vh);   cudaGetSymbolAddress((void**)&Vl, g_Vl);
    cudaGetSymbolAddress((void**)&Ah, g_Ah);   cudaGetSymbolAddress((void**)&Al, g_Al);

    cudaFuncSetAttribute(gemm_proj, cudaFuncAttributeMaxDynamicSharedMemorySize,
                         GEMM_SMEM);
    cudaFuncSetAttribute(gemm_out, cudaFuncAttributeMaxDynamicSharedMemorySize,
                         GEMM_SMEM);
    cudaFuncSetAttribute(attn_tc, cudaFuncAttributeMaxDynamicSharedMemorySize,
                         ATTN_SMEM);

    // one-launch conversion prepass
    conv_all<<<dim3(1024, 7), 256>>>(
        q_in, k_in, v_in, w_q, w_k, w_v, w_o,
        xqh, xql, xkh, xkl, xvh, xvl,
        wqh, wql, wkh, wkl, wvh, wvl, woh, wol);

    // merged Q/K/V projection GEMMs (Q output pre-scaled by 0.125*log2e)
    GemmJob jq = { xqh, xql, wqh, wql, b_q, Qh, Ql, 0.125f * 1.4426950408889634f };
    GemmJob jk = { xkh, xkl, wkh, wkl, b_k, Kh, Kl, 1.0f };
    GemmJob jv = { xvh, xvl, wvh, wvl, b_v, Vh, Vl, 1.0f };
    gemm_proj<<<dim3(32, 8, 3), 256, GEMM_SMEM>>>(jq, jk, jv);

    attn_tc<<<dim3(16, 32), 256, ATTN_SMEM>>>();

    gemm_out<<<dim3(32, 8), 256, GEMM_SMEM>>>(Ah, Al, woh, wol, b_o, out);
}

// round 12
// speedup vs baseline: 1.2595x; 1.2270x over previous
#include <cuda_runtime.h>
#include <cuda_bf16.h>
#include <cuda_fp16.h>
#include <cstdint>

#define Bn 2
#define Sn 2048
#define Dn 1024
#define Hn 16
#define DKn 64

#define NELEM (4096 * 1024)
#define WELEM (1024 * 1024)

// Scratch (device globals; no allocations allowed)
// Activations: single fp16 (hi). Weights: fp16 hi/lo. QKV: bf16 hi/lo.
__device__ __half g_xq[NELEM], g_xk[NELEM], g_xv[NELEM];
__device__ __half g_wqh[WELEM], g_wql[WELEM];
__device__ __half g_wkh[WELEM], g_wkl[WELEM];
__device__ __half g_wvh[WELEM], g_wvl[WELEM];
__device__ __half g_woh[WELEM], g_wol[WELEM];
__device__ __nv_bfloat16 g_Qh[NELEM], g_Ql[NELEM];   // [B,H,S,DK] (pre-scaled)
__device__ __nv_bfloat16 g_Kh[NELEM], g_Kl[NELEM];
__device__ __nv_bfloat16 g_Vh[NELEM], g_Vl[NELEM];
__device__ __half g_Af[NELEM];                        // attn out [B,S,D] fp16

// ---------------------------------------------------------------------------
// Helpers
// ---------------------------------------------------------------------------
__device__ __forceinline__ uint32_t smem_u32(const void* p) {
    uint32_t a;
    asm("{ .reg .u64 t; cvta.to.shared.u64 t, %1; cvt.u32.u64 %0, t; }"
        : "=r"(a) : "l"(p));
    return a;
}

__device__ __forceinline__ void ldsm_x4(uint32_t (&r)[4], uint32_t addr) {
    asm volatile("ldmatrix.sync.aligned.m8n8.x4.shared.b16 {%0,%1,%2,%3}, [%4];"
        : "=r"(r[0]), "=r"(r[1]), "=r"(r[2]), "=r"(r[3]) : "r"(addr));
}

__device__ __forceinline__ void ldsm_x4_t(uint32_t (&r)[4], uint32_t addr) {
    asm volatile("ldmatrix.sync.aligned.m8n8.x4.trans.shared.b16 {%0,%1,%2,%3}, [%4];"
        : "=r"(r[0]), "=r"(r[1]), "=r"(r[2]), "=r"(r[3]) : "r"(addr));
}

// bf16 MMA (attention)
__device__ __forceinline__ void mma16816(float (&d)[4], const uint32_t (&a)[4],
                                         uint32_t b0, uint32_t b1) {
    asm volatile(
        "mma.sync.aligned.m16n8k16.row.col.f32.bf16.bf16.f32 "
        "{%0,%1,%2,%3}, {%4,%5,%6,%7}, {%8,%9}, {%0,%1,%2,%3};"
        : "+f"(d[0]), "+f"(d[1]), "+f"(d[2]), "+f"(d[3])
        : "r"(a[0]), "r"(a[1]), "r"(a[2]), "r"(a[3]), "r"(b0), "r"(b1));
}

// fp16 MMA (GEMMs)
__device__ __forceinline__ void mma16816h(float (&d)[4], const uint32_t (&a)[4],
                                          uint32_t b0, uint32_t b1) {
    asm volatile(
        "mma.sync.aligned.m16n8k16.row.col.f32.f16.f16.f32 "
        "{%0,%1,%2,%3}, {%4,%5,%6,%7}, {%8,%9}, {%0,%1,%2,%3};"
        : "+f"(d[0]), "+f"(d[1]), "+f"(d[2]), "+f"(d[3])
        : "r"(a[0]), "r"(a[1]), "r"(a[2]), "r"(a[3]), "r"(b0), "r"(b1));
}

#define CP_ASYNC16(dst, src) \
    asm volatile("cp.async.cg.shared.global [%0], [%1], 16;" \
                 :: "r"(dst), "l"(src) : "memory")
#define CP_COMMIT()  asm volatile("cp.async.commit_group;" ::: "memory")
#define CP_WAIT0()   asm volatile("cp.async.wait_group 0;" ::: "memory")
#define CP_WAIT1()   asm volatile("cp.async.wait_group 1;" ::: "memory")

// fp16 pack (single) of a float4
__device__ __forceinline__ uint2 pack4h(float4 v) {
    uint2 o;
    o.x = ((uint32_t)__half_as_ushort(__float2half_rn(v.y)) << 16) |
          __half_as_ushort(__float2half_rn(v.x));
    o.y = ((uint32_t)__half_as_ushort(__float2half_rn(v.w)) << 16) |
          __half_as_ushort(__float2half_rn(v.z));
    return o;
}

// fp16 hi/lo split of a float4
__device__ __forceinline__ void split4h(float4 v, uint2& hi, uint2& lo) {
    __half h0 = __float2half_rn(v.x), h1 = __float2half_rn(v.y);
    __half h2 = __float2half_rn(v.z), h3 = __float2half_rn(v.w);
    __half l0 = __float2half_rn(v.x - __half2float(h0));
    __half l1 = __float2half_rn(v.y - __half2float(h1));
    __half l2 = __float2half_rn(v.z - __half2float(h2));
    __half l3 = __float2half_rn(v.w - __half2float(h3));
    hi.x = ((uint32_t)__half_as_ushort(h1) << 16) | __half_as_ushort(h0);
    hi.y = ((uint32_t)__half_as_ushort(h3) << 16) | __half_as_ushort(h2);
    lo.x = ((uint32_t)__half_as_ushort(l1) << 16) | __half_as_ushort(l0);
    lo.y = ((uint32_t)__half_as_ushort(l3) << 16) | __half_as_ushort(l2);
}

__device__ __forceinline__ uint32_t packh2(float a, float b) {
    return ((uint32_t)__half_as_ushort(__float2half_rn(b)) << 16) |
           __half_as_ushort(__float2half_rn(a));
}

// bf16 hi/lo split of a pair (QKV epilogue)
__device__ __forceinline__ void split2(float a, float b, uint32_t& hi, uint32_t& lo) {
    __nv_bfloat16 ha = __float2bfloat16_rn(a);
    __nv_bfloat16 hb = __float2bfloat16_rn(b);
    __nv_bfloat16 la = __float2bfloat16_rn(a - __bfloat162float(ha));
    __nv_bfloat16 lb = __float2bfloat16_rn(b - __bfloat162float(hb));
    hi = ((uint32_t)__bfloat16_as_ushort(hb) << 16) | __bfloat16_as_ushort(ha);
    lo = ((uint32_t)__bfloat16_as_ushort(lb) << 16) | __bfloat16_as_ushort(la);
}

__device__ __forceinline__ uint32_t packbf(float a, float b) {
    return ((uint32_t)__bfloat16_as_ushort(__float2bfloat16_rn(b)) << 16) |
           __bfloat16_as_ushort(__float2bfloat16_rn(a));
}

// Fast 2^x on the FMA pipe. Valid for x <= 0 (clamped at -126). |err|~2.4e-6.
__device__ __forceinline__ float fexp2(float x) {
    x = fmaxf(x, -126.0f);
    float n = rintf(x);
    float r = x - n;
    float p = fmaf(r, 1.3333558e-3f, 9.6181291e-3f);
    p = fmaf(r, p, 5.5504109e-2f);
    p = fmaf(r, p, 2.4022651e-1f);
    p = fmaf(r, p, 6.9314718e-1f);
    p = fmaf(r, p, 1.0f);
    int e = ((int)n + 127) << 23;
    return p * __int_as_float(e);
}

// ---------------------------------------------------------------------------
// Prepass: activations -> single fp16 ; weights -> fp16 hi/lo. One launch.
// ---------------------------------------------------------------------------
__global__ __launch_bounds__(256) void conv_all(
    const float* __restrict__ q, const float* __restrict__ k,
    const float* __restrict__ v,
    const float* __restrict__ wq, const float* __restrict__ wk,
    const float* __restrict__ wv, const float* __restrict__ wo,
    __half* xq, __half* xk, __half* xv,
    __half* wqh, __half* wql, __half* wkh, __half* wkl,
    __half* wvh, __half* wvl, __half* woh, __half* wol)
{
    const int z = blockIdx.y;
    const float* src;
    __half *H = nullptr, *L = nullptr;
    int n4;
    switch (z) {
        case 0: src = q;  H = xq;  n4 = NELEM / 4; break;
        case 1: src = k;  H = xk;  n4 = NELEM / 4; break;
        case 2: src = v;  H = xv;  n4 = NELEM / 4; break;
        case 3: src = wq; H = wqh; L = wql; n4 = WELEM / 4; break;
        case 4: src = wk; H = wkh; L = wkl; n4 = WELEM / 4; break;
        case 5: src = wv; H = wvh; L = wvl; n4 = WELEM / 4; break;
        default: src = wo; H = woh; L = wol; n4 = WELEM / 4; break;
    }
    const int base = blockIdx.x * 1024 + threadIdx.x;
    if (base >= n4) return;
#pragma unroll
    for (int u = 0; u < 4; u++) {
        const int i = base + u * 256;
        if (i < n4) {
            float4 vv = ((const float4*)src)[i];
            if (L) {
                uint2 h, l;
                split4h(vv, h, l);
                ((uint2*)H)[i] = h;
                ((uint2*)L)[i] = l;
            } else {
                ((uint2*)H)[i] = pack4h(vv);
            }
        }
    }
}

// ---------------------------------------------------------------------------
// fp16 HMMA GEMM body, 2-term (Xh*Wh + Xh*Wl), cp.async 2-stage, 2 CTAs/SM.
// Y[m,n] = sum_k X[m,k]*W[n,k] + bias[n].  Tile 128x128, BK=32, 256 thr.
// ---------------------------------------------------------------------------
#define LDA_S   80
#define MAT_SZ  (128 * LDA_S)            // 10240
#define STG_SZ  (3 * MAT_SZ)             // 30720: X, Wh, Wl
#define GEMM_SMEM (2 * STG_SZ)           // 61440

struct GemmJob {
    const __half *X, *Wh, *Wl;
    const float* bias;
    __nv_bfloat16 *Yh, *Yl;
    float oscale;
};

template <int MODE>
__device__ __forceinline__ void gemm_body(
    const __half* __restrict__ X,
    const __half* __restrict__ Wh, const __half* __restrict__ Wl,
    const float* __restrict__ bias,
    float* __restrict__ Yf,
    __nv_bfloat16* __restrict__ Yh, __nv_bfloat16* __restrict__ Yl,
    float oscale, char* sm)
{
    const uint32_t sb = smem_u32(sm);
    const int tid  = threadIdx.x;
    const int lane = tid & 31;
    const int wid  = tid >> 5;
    const int wm   = wid >> 1;
    const int wn   = wid & 1;

    const int m0 = blockIdx.x * 128;
    const int n0 = blockIdx.y * 128;
    const __half* src[3] = {
        X + (size_t)m0 * Dn, Wh + (size_t)n0 * Dn, Wl + (size_t)n0 * Dn };

    const int cr0 = (tid + 0)   >> 2;     // rows 0..63
    const int cc0 = (tid & 3)   * 16;     // 4 chunks of 16B per 64B row-slab
    const int cr1 = (tid + 256) >> 2;     // rows 64..127

    const uint32_t a_row = wm * 32 + (lane & 15);
    const uint32_t a_byt = (lane >> 4) * 16;
    const uint32_t b_row = wn * 64 + (lane & 7) + ((lane >> 4) << 3);
    const uint32_t b_byt = ((lane >> 3) & 1) * 16;

    float acc[2][8][4];
#pragma unroll
    for (int i = 0; i < 2; i++)
#pragma unroll
        for (int j = 0; j < 8; j++)
#pragma unroll
            for (int k = 0; k < 4; k++) acc[i][j][k] = 0.f;

    // prologue: stages 0,1
#pragma unroll
    for (int ps = 0; ps < 2; ps++) {
        const uint32_t st = sb + ps * STG_SZ;
#pragma unroll
        for (int mt = 0; mt < 3; mt++) {
            CP_ASYNC16(st + mt * MAT_SZ + cr0 * LDA_S + cc0,
                       src[mt] + (size_t)cr0 * Dn + ps * 32 + (cc0 >> 1));
            CP_ASYNC16(st + mt * MAT_SZ + cr1 * LDA_S + cc0,
                       src[mt] + (size_t)cr1 * Dn + ps * 32 + (cc0 >> 1));
        }
        CP_COMMIT();
    }

#pragma unroll 1
    for (int s = 0; s < 32; s++) {
        CP_WAIT1();
        __syncthreads();

        const uint32_t stg = sb + (s & 1) * STG_SZ;
#pragma unroll
        for (int ks = 0; ks < 2; ks++) {
            uint32_t ah[2][4], bh[4][4], bl[4][4];
#pragma unroll
            for (int mf = 0; mf < 2; mf++) {
                const uint32_t ao = stg + (a_row + mf * 16) * LDA_S + ks * 32 + a_byt;
                ldsm_x4(ah[mf], ao);
            }
#pragma unroll
            for (int nq = 0; nq < 4; nq++) {
                const uint32_t bo = stg + MAT_SZ +
                                    (b_row + nq * 16) * LDA_S + ks * 32 + b_byt;
                ldsm_x4(bh[nq], bo);
                ldsm_x4(bl[nq], bo + MAT_SZ);
            }
            // pass 1: X*Wh -- 16 independent MMAs
#pragma unroll
            for (int nq = 0; nq < 4; nq++)
#pragma unroll
                for (int mf = 0; mf < 2; mf++) {
                    mma16816h(acc[mf][nq * 2 + 0], ah[mf], bh[nq][0], bh[nq][1]);
                    mma16816h(acc[mf][nq * 2 + 1], ah[mf], bh[nq][2], bh[nq][3]);
                }
            // pass 2: X*Wl
#pragma unroll
            for (int nq = 0; nq < 4; nq++)
#pragma unroll
                for (int mf = 0; mf < 2; mf++) {
                    mma16816h(acc[mf][nq * 2 + 0], ah[mf], bl[nq][0], bl[nq][1]);
                    mma16816h(acc[mf][nq * 2 + 1], ah[mf], bl[nq][2], bl[nq][3]);
                }
        }

        __syncthreads();
        if (s + 2 < 32) {
            const uint32_t st = sb + (s & 1) * STG_SZ;
            const int k8 = (s + 2) * 32 + (cc0 >> 1);
#pragma unroll
            for (int mt = 0; mt < 3; mt++) {
                CP_ASYNC16(st + mt * MAT_SZ + cr0 * LDA_S + cc0,
                           src[mt] + (size_t)cr0 * Dn + k8);
                CP_ASYNC16(st + mt * MAT_SZ + cr1 * LDA_S + cc0,
                           src[mt] + (size_t)cr1 * Dn + k8);
            }
        }
        CP_COMMIT();
    }

#pragma unroll
    for (int mf = 0; mf < 2; mf++) {
        const int mr = m0 + wm * 32 + mf * 16 + (lane >> 2);
#pragma unroll
        for (int nf = 0; nf < 8; nf++) {
            const int c0 = n0 + wn * 64 + nf * 8 + (lane & 3) * 2;
            const float b0 = bias[c0], b1 = bias[c0 + 1];
#pragma unroll
            for (int rr = 0; rr < 2; rr++) {
                const int m = mr + rr * 8;
                float v0 = acc[mf][nf][rr * 2 + 0] + b0;
                float v1 = acc[mf][nf][rr * 2 + 1] + b1;
                if (MODE) {
                    v0 *= oscale; v1 *= oscale;
                    const int b = m >> 11, srow = m & (Sn - 1);
                    const int h = c0 >> 6, dk = c0 & 63;
                    const size_t idx =
                        (((size_t)(b * Hn + h)) * Sn + srow) * DKn + dk;
                    uint32_t hi, lo;
                    split2(v0, v1, hi, lo);
                    *(uint32_t*)(Yh + idx) = hi;
                    *(uint32_t*)(Yl + idx) = lo;
                } else {
                    float* dst = Yf + (size_t)m * Dn + c0;
                    dst[0] = v0; dst[1] = v1;
                }
            }
        }
    }
}

__global__ __launch_bounds__(256, 2) void gemm_proj(GemmJob a, GemmJob b, GemmJob c)
{
    extern __shared__ char sm[];
    GemmJob j = (blockIdx.z == 0) ? a : ((blockIdx.z == 1) ? b : c);
    gemm_body<1>(j.X, j.Wh, j.Wl, j.bias, nullptr, j.Yh, j.Yl, j.oscale, sm);
}

__global__ __launch_bounds__(256, 2) void gemm_out(
    const __half* X, const __half* Wh, const __half* Wl,
    const float* bias, float* Yf)
{
    extern __shared__ char sm[];
    gemm_body<0>(X, Wh, Wl, bias, Yf, nullptr, nullptr, 1.0f, sm);
}

// ---------------------------------------------------------------------------
// HMMA causal flash attention (bf16 3-term internal, unchanged numerics).
// Epilogue now writes single fp16 to g_Af.
// ---------------------------------------------------------------------------
#define LDS_B   144
#define QMAT    18432
#define KVMAT   9216
#define KV_STG  (4 * KVMAT)
#define ATTN_SMEM (2 * KV_STG)

__global__ __launch_bounds__(256, 2) void attn_tc()
{
    extern __shared__ char smem[];
    const uint32_t sb = smem_u32(smem);
    const int tid = threadIdx.x, lane = tid & 31, wid = tid >> 5;

    const int qt = 15 - blockIdx.x;
    const int bh = blockIdx.y;
    const int q0 = qt * 128;

    const size_t base = (size_t)bh * Sn * DKn;
    const __nv_bfloat16* Qh = g_Qh + base;
    const __nv_bfloat16* Ql = g_Ql + base;
    const __nv_bfloat16* Kh = g_Kh + base;
    const __nv_bfloat16* Kl = g_Kl + base;
    const __nv_bfloat16* Vh = g_Vh + base;
    const __nv_bfloat16* Vl = g_Vl + base;

    {
        char* qhd = smem + KV_STG;
        char* qld = smem + KV_STG + QMAT;
#pragma unroll
        for (int i = 0; i < 4; i++) {
            const int c = tid + i * 256;
            const int row = c >> 3, ch = c & 7;
            const uint32_t off = row * LDS_B + ch * 16;
            *(uint4*)(qhd + off) =
                *(const uint4*)(Qh + (size_t)(q0 + row) * DKn + ch * 8);
            *(uint4*)(qld + off) =
                *(const uint4*)(Ql + (size_t)(q0 + row) * DKn + ch * 8);
        }
    }
    __syncthreads();

    uint32_t qfh[4][4], qfl[4][4];
    {
        const uint32_t arow = wid * 16 + (lane & 15);
        const uint32_t abyt = (lane >> 4) * 16;
#pragma unroll
        for (int kc = 0; kc < 4; kc++) {
            const uint32_t ao = sb + KV_STG + arow * LDS_B + kc * 32 + abyt;
            ldsm_x4(qfh[kc], ao);
            ldsm_x4(qfl[kc], ao + QMAT);
        }
    }

    float accO[8][4];
#pragma unroll
    for (int j = 0; j < 8; j++)
#pragma unroll
        for (int k = 0; k < 4; k++) accO[j][k] = 0.f;
    float m_lo = -1e30f, m_hi = -1e30f, l_lo = 0.f, l_hi = 0.f;

    const int r_lo = q0 + wid * 16 + (lane >> 2);
    const int r_hi = r_lo + 8;
    const uint32_t brow = (lane & 7) + ((lane >> 4) << 3);
    const uint32_t bbyt = ((lane >> 3) & 1) * 16;
    const uint32_t vbyt = (lane >> 4) * 16;

    const int ntiles = 2 * qt + 2;

    const int lr = tid >> 3;
    const int lc = (tid & 7) * 16;
    const int le = lc >> 1;

    {
        const uint32_t st = sb;
#pragma unroll
        for (int rr = 0; rr < 2; rr++) {
            const int row = lr + rr * 32;
            const uint32_t so = row * LDS_B + lc;
            const size_t go = (size_t)row * DKn + le;
            CP_ASYNC16(st + 0 * KVMAT + so, Kh + go);
            CP_ASYNC16(st + 1 * KVMAT + so, Kl + go);
            CP_ASYNC16(st + 2 * KVMAT + so, Vh + go);
            CP_ASYNC16(st + 3 * KVMAT + so, Vl + go);
        }
        CP_COMMIT();
    }

#pragma unroll 1
    for (int kt = 0; kt < ntiles; kt++) {
        CP_WAIT0();
        __syncthreads();

        if (kt + 1 < ntiles) {
            const uint32_t st = sb + ((kt + 1) & 1) * KV_STG;
#pragma unroll
            for (int rr = 0; rr < 2; rr++) {
                const int row = lr + rr * 32;
                const uint32_t so = row * LDS_B + lc;
                const size_t go = (size_t)((kt + 1) * 64 + row) * DKn + le;
                CP_ASYNC16(st + 0 * KVMAT + so, Kh + go);
                CP_ASYNC16(st + 1 * KVMAT + so, Kl + go);
                CP_ASYNC16(st + 2 * KVMAT + so, Vh + go);
                CP_ASYNC16(st + 3 * KVMAT + so, Vl + go);
            }
        }
        CP_COMMIT();

        const uint32_t stg = sb + (kt & 1) * KV_STG;
        const int k0 = kt * 64;

        float s[8][4];
#pragma unroll
        for (int j = 0; j < 8; j++)
#pragma unroll
            for (int k = 0; k < 4; k++) s[j][k] = 0.f;

#pragma unroll
        for (int kc = 0; kc < 4; kc++) {
#pragma unroll
            for (int nq = 0; nq < 4; nq++) {
                const uint32_t bo = stg + (brow + nq * 16) * LDS_B + kc * 32 + bbyt;
                uint32_t kh[4], kl[4];
                ldsm_x4(kh, bo);
                ldsm_x4(kl, bo + KVMAT);
                mma16816(s[nq * 2 + 0], qfh[kc], kh[0], kh[1]);
                mma16816(s[nq * 2 + 1], qfh[kc], kh[2], kh[3]);
                mma16816(s[nq * 2 + 0], qfh[kc], kl[0], kl[1]);
                mma16816(s[nq * 2 + 1], qfh[kc], kl[2], kl[3]);
                mma16816(s[nq * 2 + 0], qfl[kc], kh[0], kh[1]);
                mma16816(s[nq * 2 + 1], qfl[kc], kh[2], kh[3]);
            }
        }

        if ((k0 + 63) > r_lo) {
#pragma unroll
            for (int j = 0; j < 8; j++) {
                const int c = k0 + j * 8 + (lane & 3) * 2;
                if (c > r_lo)     s[j][0] = -1e30f;
                if (c + 1 > r_lo) s[j][1] = -1e30f;
                if (c > r_hi)     s[j][2] = -1e30f;
                if (c + 1 > r_hi) s[j][3] = -1e30f;
            }
        }

        float mx0 = -1e30f, mx1 = -1e30f;
#pragma unroll
        for (int j = 0; j < 8; j++) {
            mx0 = fmaxf(mx0, fmaxf(s[j][0], s[j][1]));
            mx1 = fmaxf(mx1, fmaxf(s[j][2], s[j][3]));
        }
        mx0 = fmaxf(mx0, __shfl_xor_sync(0xffffffffu, mx0, 1));
        mx0 = fmaxf(mx0, __shfl_xor_sync(0xffffffffu, mx0, 2));
        mx1 = fmaxf(mx1, __shfl_xor_sync(0xffffffffu, mx1, 1));
        mx1 = fmaxf(mx1, __shfl_xor_sync(0xffffffffu, mx1, 2));
        const float mn0 = fmaxf(m_lo, mx0);
        const float mn1 = fmaxf(m_hi, mx1);
        const float a0 = fexp2(m_lo - mn0);
        const float a1 = fexp2(m_hi - mn1);
        m_lo = mn0; m_hi = mn1;

        float sum0 = 0.f, sum1 = 0.f;
#pragma unroll
        for (int j = 0; j < 8; j++) {
            s[j][0] = fexp2(s[j][0] - mn0);
            s[j][1] = fexp2(s[j][1] - mn0);
            s[j][2] = fexp2(s[j][2] - mn1);
            s[j][3] = fexp2(s[j][3] - mn1);
            sum0 += s[j][0] + s[j][1];
            sum1 += s[j][2] + s[j][3];
        }
        sum0 += __shfl_xor_sync(0xffffffffu, sum0, 1);
        sum0 += __shfl_xor_sync(0xffffffffu, sum0, 2);
        sum1 += __shfl_xor_sync(0xffffffffu, sum1, 1);
        sum1 += __shfl_xor_sync(0xffffffffu, sum1, 2);
        l_lo = l_lo * a0 + sum0;
        l_hi = l_hi * a1 + sum1;
#pragma unroll
        for (int j = 0; j < 8; j++) {
            accO[j][0] *= a0; accO[j][1] *= a0;
            accO[j][2] *= a1; accO[j][3] *= a1;
        }

#pragma unroll
        for (int kc = 0; kc < 4; kc++) {
            uint32_t ph[4], pl[4];
            {
                const float p00 = s[2 * kc][0],     p01 = s[2 * kc][1];
                const float p02 = s[2 * kc][2],     p03 = s[2 * kc][3];
                const float p10 = s[2 * kc + 1][0], p11 = s[2 * kc + 1][1];
                const float p12 = s[2 * kc + 1][2], p13 = s[2 * kc + 1][3];
                ph[0] = packbf(p00, p01);
                ph[1] = packbf(p02, p03);
                ph[2] = packbf(p10, p11);
                ph[3] = packbf(p12, p13);
                pl[0] = packbf(p00 - __bfloat162float(__float2bfloat16_rn(p00)),
                               p01 - __bfloat162float(__float2bfloat16_rn(p01)));
                pl[1] = packbf(p02 - __bfloat162float(__float2bfloat16_rn(p02)),
                               p03 - __bfloat162float(__float2bfloat16_rn(p03)));
                pl[2] = packbf(p10 - __bfloat162float(__float2bfloat16_rn(p10)),
                               p11 - __bfloat162float(__float2bfloat16_rn(p11)));
                pl[3] = packbf(p12 - __bfloat162float(__float2bfloat16_rn(p12)),
                               p13 - __bfloat162float(__float2bfloat16_rn(p13)));
            }
            const uint32_t vrow = kc * 16 + (lane & 15);
#pragma unroll
            for (int np = 0; np < 4; np++) {
                const uint32_t vo = stg + 2 * KVMAT + vrow * LDS_B + np * 32 + vbyt;
                uint32_t vh[4], vl[4];
                ldsm_x4_t(vh, vo);
                ldsm_x4_t(vl, vo + KVMAT);
                mma16816(accO[np * 2 + 0], ph, vh[0], vh[1]);
                mma16816(accO[np * 2 + 1], ph, vh[2], vh[3]);
                mma16816(accO[np * 2 + 0], ph, vl[0], vl[1]);
                mma16816(accO[np * 2 + 1], ph, vl[2], vl[3]);
                mma16816(accO[np * 2 + 0], pl, vh[0], vh[1]);
                mma16816(accO[np * 2 + 1], pl, vh[2], vh[3]);
            }
        }
    }

    // ---- epilogue: normalize, write single fp16 [B,S,D] ----
    const float il0 = 1.0f / l_lo;
    const float il1 = 1.0f / l_hi;
    const int b = bh >> 4, h = bh & 15;
    const int c_base = h * DKn + (lane & 3) * 2;
#pragma unroll
    for (int j = 0; j < 8; j++) {
        const int c = c_base + j * 8;
        const size_t i0 = ((size_t)(b * Sn + r_lo)) * Dn + c;
        const size_t i1 = ((size_t)(b * Sn + r_hi)) * Dn + c;
        *(uint32_t*)(g_Af + i0) = packh2(accO[j][0] * il0, accO[j][1] * il0);
        *(uint32_t*)(g_Af + i1) = packh2(accO[j][2] * il1, accO[j][3] * il1);
    }
}

// ---------------------------------------------------------------------------
extern "C" void kernel_launch(void* const* d_in, const int* in_sizes, int n_in,
                              void* d_out, int out_size)
{
    const float* k_in = (const float*)d_in[0];
    const float* q_in = (const float*)d_in[1];
    const float* v_in = (const float*)d_in[2];
    const float* w_q  = (const float*)d_in[3];
    const float* b_q  = (const float*)d_in[4];
    const float* w_k  = (const float*)d_in[5];
    const float* b_k  = (const float*)d_in[6];
    const float* w_v  = (const float*)d_in[7];
    const float* b_v  = (const float*)d_in[8];
    const float* w_o  = (const float*)d_in[9];
    const float* b_o  = (const float*)d_in[10];
    float* out = (float*)d_out;

    __half *xq, *xk, *xv;
    __half *wqh, *wql, *wkh, *wkl, *wvh, *wvl, *woh, *wol, *Af;
    __nv_bfloat16 *Qh, *Ql, *Kh, *Kl, *Vh, *Vl;
    cudaGetSymbolAddress((void**)&xq, g_xq);
    cudaGetSymbolAddress((void**)&xk, g_xk);
    cudaGetSymbolAddress((void**)&xv, g_xv);
    cudaGetSymbolAddress((void**)&wqh, g_wqh); cudaGetSymbolAddress((void**)&wql, g_wql);
    cudaGetSymbolAddress((void**)&wkh, g_wkh); cudaGetSymbolAddress((void**)&wkl, g_wkl);
    cudaGetSymbolAddress((void**)&wvh, g_wvh); cudaGetSymbolAddress((void**)&wvl, g_wvl);
    cudaGetSymbolAddress((void**)&woh, g_woh); cudaGetSymbolAddress((void**)&wol, g_wol);
    cudaGetSymbolAddress((void**)&Qh, g_Qh);   cudaGetSymbolAddress((void**)&Ql, g_Ql);
    cudaGetSymbolAddress((void**)&Kh, g_Kh);   cudaGetSymbolAddress((void**)&Kl, g_Kl);
    cudaGetSymbolAddress((void**)&Vh, g_Vh);   cudaGetSymbolAddress((void**)&Vl, g_Vl);
    cudaGetSymbolAddress((void**)&Af, g_Af);

    cudaFuncSetAttribute(gemm_proj, cudaFuncAttributeMaxDynamicSharedMemorySize,
                         GEMM_SMEM);
    cudaFuncSetAttribute(gemm_out, cudaFuncAttributeMaxDynamicSharedMemorySize,
                         GEMM_SMEM);
    cudaFuncSetAttribute(attn_tc, cudaFuncAttributeMaxDynamicSharedMemorySize,
                         ATTN_SMEM);

    // one-launch conversion prepass
    conv_all<<<dim3(1024, 7), 256>>>(
        q_in, k_in, v_in, w_q, w_k, w_v, w_o,
        xq, xk, xv,
        wqh, wql, wkh, wkl, wvh, wvl, woh, wol);

    // merged Q/K/V projection GEMMs (Q output pre-scaled by 0.125*log2e)
    GemmJob jq = { xq, wqh, wql, b_q, Qh, Ql, 0.125f * 1.4426950408889634f };
    GemmJob jk = { xk, wkh, wkl, b_k, Kh, Kl, 1.0f };
    GemmJob jv = { xv, wvh, wvl, b_v, Vh, Vl, 1.0f };
    gemm_proj<<<dim3(32, 8, 3), 256, GEMM_SMEM>>>(jq, jk, jv);

    attn_tc<<<dim3(16, 32), 256, ATTN_SMEM>>>();

    gemm_out<<<dim3(32, 8), 256, GEMM_SMEM>>>(Af, woh, wol, b_o, out);
}

// round 13
// speedup vs baseline: 1.3650x; 1.0838x over previous
#include <cuda_runtime.h>
#include <cuda_bf16.h>
#include <cuda_fp16.h>
#include <cstdint>

#define Bn 2
#define Sn 2048
#define Dn 1024
#define Hn 16
#define DKn 64

#define NELEM (4096 * 1024)
#define WELEM (1024 * 1024)

// Scratch (device globals; no allocations allowed) -- all fp16 now.
__device__ __half g_xq[NELEM], g_xk[NELEM], g_xv[NELEM];
__device__ __half g_wqh[WELEM], g_wql[WELEM];
__device__ __half g_wkh[WELEM], g_wkl[WELEM];
__device__ __half g_wvh[WELEM], g_wvl[WELEM];
__device__ __half g_woh[WELEM], g_wol[WELEM];
__device__ __half g_Qf[NELEM];                 // [B,H,S,DK] single fp16, pre-scaled
__device__ __half g_Kh[NELEM], g_Kl[NELEM];    // fp16 hi/lo
__device__ __half g_Vh[NELEM], g_Vl[NELEM];
__device__ __half g_Af[NELEM];                 // attn out [B,S,D] fp16

// ---------------------------------------------------------------------------
// Helpers
// ---------------------------------------------------------------------------
__device__ __forceinline__ uint32_t smem_u32(const void* p) {
    uint32_t a;
    asm("{ .reg .u64 t; cvta.to.shared.u64 t, %1; cvt.u32.u64 %0, t; }"
        : "=r"(a) : "l"(p));
    return a;
}

__device__ __forceinline__ void ldsm_x4(uint32_t (&r)[4], uint32_t addr) {
    asm volatile("ldmatrix.sync.aligned.m8n8.x4.shared.b16 {%0,%1,%2,%3}, [%4];"
        : "=r"(r[0]), "=r"(r[1]), "=r"(r[2]), "=r"(r[3]) : "r"(addr));
}

__device__ __forceinline__ void ldsm_x4_t(uint32_t (&r)[4], uint32_t addr) {
    asm volatile("ldmatrix.sync.aligned.m8n8.x4.trans.shared.b16 {%0,%1,%2,%3}, [%4];"
        : "=r"(r[0]), "=r"(r[1]), "=r"(r[2]), "=r"(r[3]) : "r"(addr));
}

// fp16 MMA
__device__ __forceinline__ void mma16816h(float (&d)[4], const uint32_t (&a)[4],
                                          uint32_t b0, uint32_t b1) {
    asm volatile(
        "mma.sync.aligned.m16n8k16.row.col.f32.f16.f16.f32 "
        "{%0,%1,%2,%3}, {%4,%5,%6,%7}, {%8,%9}, {%0,%1,%2,%3};"
        : "+f"(d[0]), "+f"(d[1]), "+f"(d[2]), "+f"(d[3])
        : "r"(a[0]), "r"(a[1]), "r"(a[2]), "r"(a[3]), "r"(b0), "r"(b1));
}

#define CP_ASYNC16(dst, src) \
    asm volatile("cp.async.cg.shared.global [%0], [%1], 16;" \
                 :: "r"(dst), "l"(src) : "memory")
#define CP_COMMIT()  asm volatile("cp.async.commit_group;" ::: "memory")
#define CP_WAIT0()   asm volatile("cp.async.wait_group 0;" ::: "memory")
#define CP_WAIT1()   asm volatile("cp.async.wait_group 1;" ::: "memory")

// fp16 pack (single) of a float4
__device__ __forceinline__ uint2 pack4h(float4 v) {
    uint2 o;
    o.x = ((uint32_t)__half_as_ushort(__float2half_rn(v.y)) << 16) |
          __half_as_ushort(__float2half_rn(v.x));
    o.y = ((uint32_t)__half_as_ushort(__float2half_rn(v.w)) << 16) |
          __half_as_ushort(__float2half_rn(v.z));
    return o;
}

// fp16 hi/lo split of a float4
__device__ __forceinline__ void split4h(float4 v, uint2& hi, uint2& lo) {
    __half h0 = __float2half_rn(v.x), h1 = __float2half_rn(v.y);
    __half h2 = __float2half_rn(v.z), h3 = __float2half_rn(v.w);
    __half l0 = __float2half_rn(v.x - __half2float(h0));
    __half l1 = __float2half_rn(v.y - __half2float(h1));
    __half l2 = __float2half_rn(v.z - __half2float(h2));
    __half l3 = __float2half_rn(v.w - __half2float(h3));
    hi.x = ((uint32_t)__half_as_ushort(h1) << 16) | __half_as_ushort(h0);
    hi.y = ((uint32_t)__half_as_ushort(h3) << 16) | __half_as_ushort(h2);
    lo.x = ((uint32_t)__half_as_ushort(l1) << 16) | __half_as_ushort(l0);
    lo.y = ((uint32_t)__half_as_ushort(l3) << 16) | __half_as_ushort(l2);
}

// fp16 hi/lo split of a pair
__device__ __forceinline__ void split2h(float a, float b, uint32_t& hi, uint32_t& lo) {
    __half ha = __float2half_rn(a), hb = __float2half_rn(b);
    __half la = __float2half_rn(a - __half2float(ha));
    __half lb = __float2half_rn(b - __half2float(hb));
    hi = ((uint32_t)__half_as_ushort(hb) << 16) | __half_as_ushort(ha);
    lo = ((uint32_t)__half_as_ushort(lb) << 16) | __half_as_ushort(la);
}

__device__ __forceinline__ uint32_t packh2(float a, float b) {
    return ((uint32_t)__half_as_ushort(__float2half_rn(b)) << 16) |
           __half_as_ushort(__float2half_rn(a));
}

// Fast 2^x on the FMA pipe. Valid for x <= 0 (clamped at -126). |err|~2.4e-6.
__device__ __forceinline__ float fexp2(float x) {
    x = fmaxf(x, -126.0f);
    float n = rintf(x);
    float r = x - n;
    float p = fmaf(r, 1.3333558e-3f, 9.6181291e-3f);
    p = fmaf(r, p, 5.5504109e-2f);
    p = fmaf(r, p, 2.4022651e-1f);
    p = fmaf(r, p, 6.9314718e-1f);
    p = fmaf(r, p, 1.0f);
    int e = ((int)n + 127) << 23;
    return p * __int_as_float(e);
}

// ---------------------------------------------------------------------------
// Prepass: activations -> single fp16 ; weights -> fp16 hi/lo. One launch.
// ---------------------------------------------------------------------------
__global__ __launch_bounds__(256) void conv_all(
    const float* __restrict__ q, const float* __restrict__ k,
    const float* __restrict__ v,
    const float* __restrict__ wq, const float* __restrict__ wk,
    const float* __restrict__ wv, const float* __restrict__ wo,
    __half* xq, __half* xk, __half* xv,
    __half* wqh, __half* wql, __half* wkh, __half* wkl,
    __half* wvh, __half* wvl, __half* woh, __half* wol)
{
    const int z = blockIdx.y;
    const float* src;
    __half *H = nullptr, *L = nullptr;
    int n4;
    switch (z) {
        case 0: src = q;  H = xq;  n4 = NELEM / 4; break;
        case 1: src = k;  H = xk;  n4 = NELEM / 4; break;
        case 2: src = v;  H = xv;  n4 = NELEM / 4; break;
        case 3: src = wq; H = wqh; L = wql; n4 = WELEM / 4; break;
        case 4: src = wk; H = wkh; L = wkl; n4 = WELEM / 4; break;
        case 5: src = wv; H = wvh; L = wvl; n4 = WELEM / 4; break;
        default: src = wo; H = woh; L = wol; n4 = WELEM / 4; break;
    }
    const int base = blockIdx.x * 1024 + threadIdx.x;
    if (base >= n4) return;
#pragma unroll
    for (int u = 0; u < 4; u++) {
        const int i = base + u * 256;
        if (i < n4) {
            float4 vv = ((const float4*)src)[i];
            if (L) {
                uint2 h, l;
                split4h(vv, h, l);
                ((uint2*)H)[i] = h;
                ((uint2*)L)[i] = l;
            } else {
                ((uint2*)H)[i] = pack4h(vv);
            }
        }
    }
}

// ---------------------------------------------------------------------------
// fp16 HMMA GEMM body, 2-term (X*Wh + X*Wl), cp.async 2-stage, 2 CTAs/SM.
// MODE 1: fp16 out permuted [B,H,S,DK] (Yl null -> single; else hi/lo).
// MODE 0: fp32 row-major out.
// ---------------------------------------------------------------------------
#define LDA_S   80
#define MAT_SZ  (128 * LDA_S)            // 10240
#define STG_SZ  (3 * MAT_SZ)             // 30720: X, Wh, Wl
#define GEMM_SMEM (2 * STG_SZ)           // 61440

struct GemmJob {
    const __half *X, *Wh, *Wl;
    const float* bias;
    __half *Yh, *Yl;                     // Yl == nullptr -> single fp16 out
    float oscale;
};

template <int MODE>
__device__ __forceinline__ void gemm_body(
    const __half* __restrict__ X,
    const __half* __restrict__ Wh, const __half* __restrict__ Wl,
    const float* __restrict__ bias,
    float* __restrict__ Yf,
    __half* __restrict__ Yh, __half* __restrict__ Yl,
    float oscale, char* sm)
{
    const uint32_t sb = smem_u32(sm);
    const int tid  = threadIdx.x;
    const int lane = tid & 31;
    const int wid  = tid >> 5;
    const int wm   = wid >> 1;
    const int wn   = wid & 1;

    const int m0 = blockIdx.x * 128;
    const int n0 = blockIdx.y * 128;
    const __half* src[3] = {
        X + (size_t)m0 * Dn, Wh + (size_t)n0 * Dn, Wl + (size_t)n0 * Dn };

    const int cr0 = (tid + 0)   >> 2;
    const int cc0 = (tid & 3)   * 16;
    const int cr1 = (tid + 256) >> 2;

    const uint32_t a_row = wm * 32 + (lane & 15);
    const uint32_t a_byt = (lane >> 4) * 16;
    const uint32_t b_row = wn * 64 + (lane & 7) + ((lane >> 4) << 3);
    const uint32_t b_byt = ((lane >> 3) & 1) * 16;

    float acc[2][8][4];
#pragma unroll
    for (int i = 0; i < 2; i++)
#pragma unroll
        for (int j = 0; j < 8; j++)
#pragma unroll
            for (int k = 0; k < 4; k++) acc[i][j][k] = 0.f;

#pragma unroll
    for (int ps = 0; ps < 2; ps++) {
        const uint32_t st = sb + ps * STG_SZ;
#pragma unroll
        for (int mt = 0; mt < 3; mt++) {
            CP_ASYNC16(st + mt * MAT_SZ + cr0 * LDA_S + cc0,
                       src[mt] + (size_t)cr0 * Dn + ps * 32 + (cc0 >> 1));
            CP_ASYNC16(st + mt * MAT_SZ + cr1 * LDA_S + cc0,
                       src[mt] + (size_t)cr1 * Dn + ps * 32 + (cc0 >> 1));
        }
        CP_COMMIT();
    }

#pragma unroll 1
    for (int s = 0; s < 32; s++) {
        CP_WAIT1();
        __syncthreads();

        const uint32_t stg = sb + (s & 1) * STG_SZ;
#pragma unroll
        for (int ks = 0; ks < 2; ks++) {
            uint32_t ah[2][4], bh[4][4], bl[4][4];
#pragma unroll
            for (int mf = 0; mf < 2; mf++) {
                const uint32_t ao = stg + (a_row + mf * 16) * LDA_S + ks * 32 + a_byt;
                ldsm_x4(ah[mf], ao);
            }
#pragma unroll
            for (int nq = 0; nq < 4; nq++) {
                const uint32_t bo = stg + MAT_SZ +
                                    (b_row + nq * 16) * LDA_S + ks * 32 + b_byt;
                ldsm_x4(bh[nq], bo);
                ldsm_x4(bl[nq], bo + MAT_SZ);
            }
#pragma unroll
            for (int nq = 0; nq < 4; nq++)
#pragma unroll
                for (int mf = 0; mf < 2; mf++) {
                    mma16816h(acc[mf][nq * 2 + 0], ah[mf], bh[nq][0], bh[nq][1]);
                    mma16816h(acc[mf][nq * 2 + 1], ah[mf], bh[nq][2], bh[nq][3]);
                }
#pragma unroll
            for (int nq = 0; nq < 4; nq++)
#pragma unroll
                for (int mf = 0; mf < 2; mf++) {
                    mma16816h(acc[mf][nq * 2 + 0], ah[mf], bl[nq][0], bl[nq][1]);
                    mma16816h(acc[mf][nq * 2 + 1], ah[mf], bl[nq][2], bl[nq][3]);
                }
        }

        __syncthreads();
        if (s + 2 < 32) {
            const uint32_t st = sb + (s & 1) * STG_SZ;
            const int k8 = (s + 2) * 32 + (cc0 >> 1);
#pragma unroll
            for (int mt = 0; mt < 3; mt++) {
                CP_ASYNC16(st + mt * MAT_SZ + cr0 * LDA_S + cc0,
                           src[mt] + (size_t)cr0 * Dn + k8);
                CP_ASYNC16(st + mt * MAT_SZ + cr1 * LDA_S + cc0,
                           src[mt] + (size_t)cr1 * Dn + k8);
            }
        }
        CP_COMMIT();
    }

#pragma unroll
    for (int mf = 0; mf < 2; mf++) {
        const int mr = m0 + wm * 32 + mf * 16 + (lane >> 2);
#pragma unroll
        for (int nf = 0; nf < 8; nf++) {
            const int c0 = n0 + wn * 64 + nf * 8 + (lane & 3) * 2;
            const float b0 = bias[c0], b1 = bias[c0 + 1];
#pragma unroll
            for (int rr = 0; rr < 2; rr++) {
                const int m = mr + rr * 8;
                float v0 = acc[mf][nf][rr * 2 + 0] + b0;
                float v1 = acc[mf][nf][rr * 2 + 1] + b1;
                if (MODE) {
                    v0 *= oscale; v1 *= oscale;
                    const int b = m >> 11, srow = m & (Sn - 1);
                    const int h = c0 >> 6, dk = c0 & 63;
                    const size_t idx =
                        (((size_t)(b * Hn + h)) * Sn + srow) * DKn + dk;
                    if (Yl) {
                        uint32_t hi, lo;
                        split2h(v0, v1, hi, lo);
                        *(uint32_t*)(Yh + idx) = hi;
                        *(uint32_t*)(Yl + idx) = lo;
                    } else {
                        *(uint32_t*)(Yh + idx) = packh2(v0, v1);
                    }
                } else {
                    float* dst = Yf + (size_t)m * Dn + c0;
                    dst[0] = v0; dst[1] = v1;
                }
            }
        }
    }
}

__global__ __launch_bounds__(256, 2) void gemm_proj(GemmJob a, GemmJob b, GemmJob c)
{
    extern __shared__ char sm[];
    GemmJob j = (blockIdx.z == 0) ? a : ((blockIdx.z == 1) ? b : c);
    gemm_body<1>(j.X, j.Wh, j.Wl, j.bias, nullptr, j.Yh, j.Yl, j.oscale, sm);
}

__global__ __launch_bounds__(256, 2) void gemm_out(
    const __half* X, const __half* Wh, const __half* Wl,
    const float* bias, float* Yf)
{
    extern __shared__ char sm[];
    gemm_body<0>(X, Wh, Wl, bias, Yf, nullptr, nullptr, 1.0f, sm);
}

// ---------------------------------------------------------------------------
// fp16 HMMA causal flash attention, 2-term (Qf single; K,V hi/lo).
// 128 q-rows per CTA, KV tiles of 64, cp.async double-buffered, 2 CTAs/SM.
// Scores in log2 domain (Q pre-scaled by 0.125*log2e), fexp2 softmax.
// ---------------------------------------------------------------------------
#define LDS_B   144
#define QMAT    18432                  // 128 * 144 (single Q)
#define KVMAT   9216                   // 64 * 144
#define KV_STG  (4 * KVMAT)            // Kh,Kl,Vh,Vl
#define ATTN_SMEM (2 * KV_STG)         // 73728 (Q staged in buf1 then reused)

__global__ __launch_bounds__(256, 2) void attn_tc()
{
    extern __shared__ char smem[];
    const uint32_t sb = smem_u32(smem);
    const int tid = threadIdx.x, lane = tid & 31, wid = tid >> 5;

    const int qt = 15 - blockIdx.x;       // heavy blocks first
    const int bh = blockIdx.y;
    const int q0 = qt * 128;

    const size_t base = (size_t)bh * Sn * DKn;
    const __half* Qf = g_Qf + base;
    const __half* Kh = g_Kh + base;
    const __half* Kl = g_Kl + base;
    const __half* Vh = g_Vh + base;
    const __half* Vl = g_Vl + base;

    // ---- stage Q (single fp16) into buf1, pull into A-frags ----
    {
        char* qd = smem + KV_STG;
#pragma unroll
        for (int i = 0; i < 4; i++) {
            const int c = tid + i * 256;        // 1024 chunks of 16B
            const int row = c >> 3, ch = c & 7;
            *(uint4*)(qd + row * LDS_B + ch * 16) =
                *(const uint4*)(Qf + (size_t)(q0 + row) * DKn + ch * 8);
        }
    }
    __syncthreads();

    uint32_t qf[4][4];
    {
        const uint32_t arow = wid * 16 + (lane & 15);
        const uint32_t abyt = (lane >> 4) * 16;
#pragma unroll
        for (int kc = 0; kc < 4; kc++)
            ldsm_x4(qf[kc], sb + KV_STG + arow * LDS_B + kc * 32 + abyt);
    }

    float accO[8][4];
#pragma unroll
    for (int j = 0; j < 8; j++)
#pragma unroll
        for (int k = 0; k < 4; k++) accO[j][k] = 0.f;
    float m_lo = -1e30f, m_hi = -1e30f, l_lo = 0.f, l_hi = 0.f;

    const int r_lo = q0 + wid * 16 + (lane >> 2);
    const int r_hi = r_lo + 8;
    const uint32_t brow = (lane & 7) + ((lane >> 4) << 3);
    const uint32_t bbyt = ((lane >> 3) & 1) * 16;
    const uint32_t vbyt = (lane >> 4) * 16;

    const int ntiles = 2 * qt + 2;

    const int lr = tid >> 3;              // 0..31
    const int lc = (tid & 7) * 16;
    const int le = lc >> 1;

    {
        const uint32_t st = sb;
#pragma unroll
        for (int rr = 0; rr < 2; rr++) {
            const int row = lr + rr * 32;
            const uint32_t so = row * LDS_B + lc;
            const size_t go = (size_t)row * DKn + le;
            CP_ASYNC16(st + 0 * KVMAT + so, Kh + go);
            CP_ASYNC16(st + 1 * KVMAT + so, Kl + go);
            CP_ASYNC16(st + 2 * KVMAT + so, Vh + go);
            CP_ASYNC16(st + 3 * KVMAT + so, Vl + go);
        }
        CP_COMMIT();
    }

#pragma unroll 1
    for (int kt = 0; kt < ntiles; kt++) {
        CP_WAIT0();
        __syncthreads();

        if (kt + 1 < ntiles) {
            const uint32_t st = sb + ((kt + 1) & 1) * KV_STG;
#pragma unroll
            for (int rr = 0; rr < 2; rr++) {
                const int row = lr + rr * 32;
                const uint32_t so = row * LDS_B + lc;
                const size_t go = (size_t)((kt + 1) * 64 + row) * DKn + le;
                CP_ASYNC16(st + 0 * KVMAT + so, Kh + go);
                CP_ASYNC16(st + 1 * KVMAT + so, Kl + go);
                CP_ASYNC16(st + 2 * KVMAT + so, Vh + go);
                CP_ASYNC16(st + 3 * KVMAT + so, Vl + go);
            }
        }
        CP_COMMIT();

        const uint32_t stg = sb + (kt & 1) * KV_STG;
        const int k0 = kt * 64;

        // ---- S = Q K^T (2-term fp16), log2-domain scores ----
        float s[8][4];
#pragma unroll
        for (int j = 0; j < 8; j++)
#pragma unroll
            for (int k = 0; k < 4; k++) s[j][k] = 0.f;

#pragma unroll
        for (int kc = 0; kc < 4; kc++) {
#pragma unroll
            for (int nq = 0; nq < 4; nq++) {
                const uint32_t bo = stg + (brow + nq * 16) * LDS_B + kc * 32 + bbyt;
                uint32_t kh[4], kl[4];
                ldsm_x4(kh, bo);
                ldsm_x4(kl, bo + KVMAT);
                mma16816h(s[nq * 2 + 0], qf[kc], kh[0], kh[1]);
                mma16816h(s[nq * 2 + 1], qf[kc], kh[2], kh[3]);
                mma16816h(s[nq * 2 + 0], qf[kc], kl[0], kl[1]);
                mma16816h(s[nq * 2 + 1], qf[kc], kl[2], kl[3]);
            }
        }

        // ---- causal mask ----
        if ((k0 + 63) > r_lo) {
#pragma unroll
            for (int j = 0; j < 8; j++) {
                const int c = k0 + j * 8 + (lane & 3) * 2;
                if (c > r_lo)     s[j][0] = -1e30f;
                if (c + 1 > r_lo) s[j][1] = -1e30f;
                if (c > r_hi)     s[j][2] = -1e30f;
                if (c + 1 > r_hi) s[j][3] = -1e30f;
            }
        }

        // ---- online softmax (base-2) ----
        float mx0 = -1e30f, mx1 = -1e30f;
#pragma unroll
        for (int j = 0; j < 8; j++) {
            mx0 = fmaxf(mx0, fmaxf(s[j][0], s[j][1]));
            mx1 = fmaxf(mx1, fmaxf(s[j][2], s[j][3]));
        }
        mx0 = fmaxf(mx0, __shfl_xor_sync(0xffffffffu, mx0, 1));
        mx0 = fmaxf(mx0, __shfl_xor_sync(0xffffffffu, mx0, 2));
        mx1 = fmaxf(mx1, __shfl_xor_sync(0xffffffffu, mx1, 1));
        mx1 = fmaxf(mx1, __shfl_xor_sync(0xffffffffu, mx1, 2));
        const float mn0 = fmaxf(m_lo, mx0);
        const float mn1 = fmaxf(m_hi, mx1);
        const float a0 = fexp2(m_lo - mn0);
        const float a1 = fexp2(m_hi - mn1);
        m_lo = mn0; m_hi = mn1;

        float sum0 = 0.f, sum1 = 0.f;
#pragma unroll
        for (int j = 0; j < 8; j++) {
            s[j][0] = fexp2(s[j][0] - mn0);
            s[j][1] = fexp2(s[j][1] - mn0);
            s[j][2] = fexp2(s[j][2] - mn1);
            s[j][3] = fexp2(s[j][3] - mn1);
            sum0 += s[j][0] + s[j][1];
            sum1 += s[j][2] + s[j][3];
        }
        sum0 += __shfl_xor_sync(0xffffffffu, sum0, 1);
        sum0 += __shfl_xor_sync(0xffffffffu, sum0, 2);
        sum1 += __shfl_xor_sync(0xffffffffu, sum1, 1);
        sum1 += __shfl_xor_sync(0xffffffffu, sum1, 2);
        l_lo = l_lo * a0 + sum0;
        l_hi = l_hi * a1 + sum1;
#pragma unroll
        for (int j = 0; j < 8; j++) {
            accO[j][0] *= a0; accO[j][1] *= a0;
            accO[j][2] *= a1; accO[j][3] *= a1;
        }

        // ---- O += P V (2-term fp16, P single) ----
#pragma unroll
        for (int kc = 0; kc < 4; kc++) {
            uint32_t ph[4];
            ph[0] = packh2(s[2 * kc][0],     s[2 * kc][1]);
            ph[1] = packh2(s[2 * kc][2],     s[2 * kc][3]);
            ph[2] = packh2(s[2 * kc + 1][0], s[2 * kc + 1][1]);
            ph[3] = packh2(s[2 * kc + 1][2], s[2 * kc + 1][3]);
            const uint32_t vrow = kc * 16 + (lane & 15);
#pragma unroll
            for (int np = 0; np < 4; np++) {
                const uint32_t vo = stg + 2 * KVMAT + vrow * LDS_B + np * 32 + vbyt;
                uint32_t vh[4], vl[4];
                ldsm_x4_t(vh, vo);
                ldsm_x4_t(vl, vo + KVMAT);
                mma16816h(accO[np * 2 + 0], ph, vh[0], vh[1]);
                mma16816h(accO[np * 2 + 1], ph, vh[2], vh[3]);
                mma16816h(accO[np * 2 + 0], ph, vl[0], vl[1]);
                mma16816h(accO[np * 2 + 1], ph, vl[2], vl[3]);
            }
        }
    }

    // ---- epilogue: normalize, write single fp16 [B,S,D] ----
    const float il0 = 1.0f / l_lo;
    const float il1 = 1.0f / l_hi;
    const int b = bh >> 4, h = bh & 15;
    const int c_base = h * DKn + (lane & 3) * 2;
#pragma unroll
    for (int j = 0; j < 8; j++) {
        const int c = c_base + j * 8;
        const size_t i0 = ((size_t)(b * Sn + r_lo)) * Dn + c;
        const size_t i1 = ((size_t)(b * Sn + r_hi)) * Dn + c;
        *(uint32_t*)(g_Af + i0) = packh2(accO[j][0] * il0, accO[j][1] * il0);
        *(uint32_t*)(g_Af + i1) = packh2(accO[j][2] * il1, accO[j][3] * il1);
    }
}

// ---------------------------------------------------------------------------
extern "C" void kernel_launch(void* const* d_in, const int* in_sizes, int n_in,
                              void* d_out, int out_size)
{
    const float* k_in = (const float*)d_in[0];
    const float* q_in = (const float*)d_in[1];
    const float* v_in = (const float*)d_in[2];
    const float* w_q  = (const float*)d_in[3];
    const float* b_q  = (const float*)d_in[4];
    const float* w_k  = (const float*)d_in[5];
    const float* b_k  = (const float*)d_in[6];
    const float* w_v  = (const float*)d_in[7];
    const float* b_v  = (const float*)d_in[8];
    const float* w_o  = (const float*)d_in[9];
    const float* b_o  = (const float*)d_in[10];
    float* out = (float*)d_out;

    __half *xq, *xk, *xv;
    __half *wqh, *wql, *wkh, *wkl, *wvh, *wvl, *woh, *wol;
    __half *Qf, *Kh, *Kl, *Vh, *Vl, *Af;
    cudaGetSymbolAddress((void**)&xq, g_xq);
    cudaGetSymbolAddress((void**)&xk, g_xk);
    cudaGetSymbolAddress((void**)&xv, g_xv);
    cudaGetSymbolAddress((void**)&wqh, g_wqh); cudaGetSymbolAddress((void**)&wql, g_wql);
    cudaGetSymbolAddress((void**)&wkh, g_wkh); cudaGetSymbolAddress((void**)&wkl, g_wkl);
    cudaGetSymbolAddress((void**)&wvh, g_wvh); cudaGetSymbolAddress((void**)&wvl, g_wvl);
    cudaGetSymbolAddress((void**)&woh, g_woh); cudaGetSymbolAddress((void**)&wol, g_wol);
    cudaGetSymbolAddress((void**)&Qf, g_Qf);
    cudaGetSymbolAddress((void**)&Kh, g_Kh);   cudaGetSymbolAddress((void**)&Kl, g_Kl);
    cudaGetSymbolAddress((void**)&Vh, g_Vh);   cudaGetSymbolAddress((void**)&Vl, g_Vl);
    cudaGetSymbolAddress((void**)&Af, g_Af);

    cudaFuncSetAttribute(gemm_proj, cudaFuncAttributeMaxDynamicSharedMemorySize,
                         GEMM_SMEM);
    cudaFuncSetAttribute(gemm_out, cudaFuncAttributeMaxDynamicSharedMemorySize,
                         GEMM_SMEM);
    cudaFuncSetAttribute(attn_tc, cudaFuncAttributeMaxDynamicSharedMemorySize,
                         ATTN_SMEM);

    // one-launch conversion prepass
    conv_all<<<dim3(1024, 7), 256>>>(
        q_in, k_in, v_in, w_q, w_k, w_v, w_o,
        xq, xk, xv,
        wqh, wql, wkh, wkl, wvh, wvl, woh, wol);

    // merged Q/K/V projection GEMMs
    // Q: single fp16 out, pre-scaled by 0.125*log2e. K/V: fp16 hi/lo.
    GemmJob jq = { xq, wqh, wql, b_q, Qf, nullptr, 0.125f * 1.4426950408889634f };
    GemmJob jk = { xk, wkh, wkl, b_k, Kh, Kl, 1.0f };
    GemmJob jv = { xv, wvh, wvl, b_v, Vh, Vl, 1.0f };
    gemm_proj<<<dim3(32, 8, 3), 256, GEMM_SMEM>>>(jq, jk, jv);

    attn_tc<<<dim3(16, 32), 256, ATTN_SMEM>>>();

    gemm_out<<<dim3(32, 8), 256, GEMM_SMEM>>>(Af, woh, wol, b_o, out);
}

// round 14
// speedup vs baseline: 1.6603x; 1.2163x over previous
#include <cuda_runtime.h>
#include <cuda_bf16.h>
#include <cuda_fp16.h>
#include <cstdint>

#define Bn 2
#define Sn 2048
#define Dn 1024
#define Hn 16
#define DKn 64

#define NELEM (4096 * 1024)
#define WELEM (1024 * 1024)

// Scratch (device globals; no allocations allowed) -- all fp16.
__device__ __half g_xq[NELEM], g_xk[NELEM], g_xv[NELEM];
__device__ __half g_wqh[WELEM], g_wql[WELEM];
__device__ __half g_wkh[WELEM], g_wkl[WELEM];
__device__ __half g_wvh[WELEM], g_wvl[WELEM];
__device__ __half g_woh[WELEM], g_wol[WELEM];
__device__ __half g_Qf[NELEM];                 // [B,H,S,DK] single fp16, pre-scaled
__device__ __half g_Kf[NELEM];                 // single fp16
__device__ __half g_Vf[NELEM];                 // single fp16
__device__ __half g_Af[NELEM];                 // attn out [B,S,D] fp16

// ---------------------------------------------------------------------------
// Helpers
// ---------------------------------------------------------------------------
__device__ __forceinline__ uint32_t smem_u32(const void* p) {
    uint32_t a;
    asm("{ .reg .u64 t; cvta.to.shared.u64 t, %1; cvt.u32.u64 %0, t; }"
        : "=r"(a) : "l"(p));
    return a;
}

__device__ __forceinline__ void ldsm_x4(uint32_t (&r)[4], uint32_t addr) {
    asm volatile("ldmatrix.sync.aligned.m8n8.x4.shared.b16 {%0,%1,%2,%3}, [%4];"
        : "=r"(r[0]), "=r"(r[1]), "=r"(r[2]), "=r"(r[3]) : "r"(addr));
}

__device__ __forceinline__ void ldsm_x4_t(uint32_t (&r)[4], uint32_t addr) {
    asm volatile("ldmatrix.sync.aligned.m8n8.x4.trans.shared.b16 {%0,%1,%2,%3}, [%4];"
        : "=r"(r[0]), "=r"(r[1]), "=r"(r[2]), "=r"(r[3]) : "r"(addr));
}

// fp16 MMA
__device__ __forceinline__ void mma16816h(float (&d)[4], const uint32_t (&a)[4],
                                          uint32_t b0, uint32_t b1) {
    asm volatile(
        "mma.sync.aligned.m16n8k16.row.col.f32.f16.f16.f32 "
        "{%0,%1,%2,%3}, {%4,%5,%6,%7}, {%8,%9}, {%0,%1,%2,%3};"
        : "+f"(d[0]), "+f"(d[1]), "+f"(d[2]), "+f"(d[3])
        : "r"(a[0]), "r"(a[1]), "r"(a[2]), "r"(a[3]), "r"(b0), "r"(b1));
}

#define CP_ASYNC16(dst, src) \
    asm volatile("cp.async.cg.shared.global [%0], [%1], 16;" \
                 :: "r"(dst), "l"(src) : "memory")
#define CP_COMMIT()  asm volatile("cp.async.commit_group;" ::: "memory")
#define CP_WAIT0()   asm volatile("cp.async.wait_group 0;" ::: "memory")
#define CP_WAIT1()   asm volatile("cp.async.wait_group 1;" ::: "memory")

// fp16 pack (single) of a float4
__device__ __forceinline__ uint2 pack4h(float4 v) {
    uint2 o;
    o.x = ((uint32_t)__half_as_ushort(__float2half_rn(v.y)) << 16) |
          __half_as_ushort(__float2half_rn(v.x));
    o.y = ((uint32_t)__half_as_ushort(__float2half_rn(v.w)) << 16) |
          __half_as_ushort(__float2half_rn(v.z));
    return o;
}

// fp16 hi/lo split of a float4
__device__ __forceinline__ void split4h(float4 v, uint2& hi, uint2& lo) {
    __half h0 = __float2half_rn(v.x), h1 = __float2half_rn(v.y);
    __half h2 = __float2half_rn(v.z), h3 = __float2half_rn(v.w);
    __half l0 = __float2half_rn(v.x - __half2float(h0));
    __half l1 = __float2half_rn(v.y - __half2float(h1));
    __half l2 = __float2half_rn(v.z - __half2float(h2));
    __half l3 = __float2half_rn(v.w - __half2float(h3));
    hi.x = ((uint32_t)__half_as_ushort(h1) << 16) | __half_as_ushort(h0);
    hi.y = ((uint32_t)__half_as_ushort(h3) << 16) | __half_as_ushort(h2);
    lo.x = ((uint32_t)__half_as_ushort(l1) << 16) | __half_as_ushort(l0);
    lo.y = ((uint32_t)__half_as_ushort(l3) << 16) | __half_as_ushort(l2);
}

__device__ __forceinline__ uint32_t packh2(float a, float b) {
    return ((uint32_t)__half_as_ushort(__float2half_rn(b)) << 16) |
           __half_as_ushort(__float2half_rn(a));
}

// Fast 2^x on the FMA pipe. Valid for x <= 0 (clamped at -126). |err|~2.4e-6.
__device__ __forceinline__ float fexp2(float x) {
    x = fmaxf(x, -126.0f);
    float n = rintf(x);
    float r = x - n;
    float p = fmaf(r, 1.3333558e-3f, 9.6181291e-3f);
    p = fmaf(r, p, 5.5504109e-2f);
    p = fmaf(r, p, 2.4022651e-1f);
    p = fmaf(r, p, 6.9314718e-1f);
    p = fmaf(r, p, 1.0f);
    int e = ((int)n + 127) << 23;
    return p * __int_as_float(e);
}

// ---------------------------------------------------------------------------
// Prepass: activations -> single fp16 ; weights -> fp16 hi/lo. One launch.
// ---------------------------------------------------------------------------
__global__ __launch_bounds__(256) void conv_all(
    const float* __restrict__ q, const float* __restrict__ k,
    const float* __restrict__ v,
    const float* __restrict__ wq, const float* __restrict__ wk,
    const float* __restrict__ wv, const float* __restrict__ wo,
    __half* xq, __half* xk, __half* xv,
    __half* wqh, __half* wql, __half* wkh, __half* wkl,
    __half* wvh, __half* wvl, __half* woh, __half* wol)
{
    const int z = blockIdx.y;
    const float* src;
    __half *H = nullptr, *L = nullptr;
    int n4;
    switch (z) {
        case 0: src = q;  H = xq;  n4 = NELEM / 4; break;
        case 1: src = k;  H = xk;  n4 = NELEM / 4; break;
        case 2: src = v;  H = xv;  n4 = NELEM / 4; break;
        case 3: src = wq; H = wqh; L = wql; n4 = WELEM / 4; break;
        case 4: src = wk; H = wkh; L = wkl; n4 = WELEM / 4; break;
        case 5: src = wv; H = wvh; L = wvl; n4 = WELEM / 4; break;
        default: src = wo; H = woh; L = wol; n4 = WELEM / 4; break;
    }
    const int base = blockIdx.x * 1024 + threadIdx.x;
    if (base >= n4) return;
#pragma unroll
    for (int u = 0; u < 4; u++) {
        const int i = base + u * 256;
        if (i < n4) {
            float4 vv = ((const float4*)src)[i];
            if (L) {
                uint2 h, l;
                split4h(vv, h, l);
                ((uint2*)H)[i] = h;
                ((uint2*)L)[i] = l;
            } else {
                ((uint2*)H)[i] = pack4h(vv);
            }
        }
    }
}

// ---------------------------------------------------------------------------
// fp16 HMMA GEMM body, 2-term (X*Wh + X*Wl), cp.async 2-stage, 2 CTAs/SM.
// MODE 1: single fp16 out permuted [B,H,S,DK]. MODE 0: fp32 row-major out.
// ---------------------------------------------------------------------------
#define LDA_S   80
#define MAT_SZ  (128 * LDA_S)            // 10240
#define STG_SZ  (3 * MAT_SZ)             // 30720: X, Wh, Wl
#define GEMM_SMEM (2 * STG_SZ)           // 61440

struct GemmJob {
    const __half *X, *Wh, *Wl;
    const float* bias;
    __half *Y;
    float oscale;
};

template <int MODE>
__device__ __forceinline__ void gemm_body(
    const __half* __restrict__ X,
    const __half* __restrict__ Wh, const __half* __restrict__ Wl,
    const float* __restrict__ bias,
    float* __restrict__ Yf,
    __half* __restrict__ Yh,
    float oscale, char* sm)
{
    const uint32_t sb = smem_u32(sm);
    const int tid  = threadIdx.x;
    const int lane = tid & 31;
    const int wid  = tid >> 5;
    const int wm   = wid >> 1;
    const int wn   = wid & 1;

    const int m0 = blockIdx.x * 128;
    const int n0 = blockIdx.y * 128;
    const __half* src[3] = {
        X + (size_t)m0 * Dn, Wh + (size_t)n0 * Dn, Wl + (size_t)n0 * Dn };

    const int cr0 = (tid + 0)   >> 2;
    const int cc0 = (tid & 3)   * 16;
    const int cr1 = (tid + 256) >> 2;

    const uint32_t a_row = wm * 32 + (lane & 15);
    const uint32_t a_byt = (lane >> 4) * 16;
    const uint32_t b_row = wn * 64 + (lane & 7) + ((lane >> 4) << 3);
    const uint32_t b_byt = ((lane >> 3) & 1) * 16;

    float acc[2][8][4];
#pragma unroll
    for (int i = 0; i < 2; i++)
#pragma unroll
        for (int j = 0; j < 8; j++)
#pragma unroll
            for (int k = 0; k < 4; k++) acc[i][j][k] = 0.f;

#pragma unroll
    for (int ps = 0; ps < 2; ps++) {
        const uint32_t st = sb + ps * STG_SZ;
#pragma unroll
        for (int mt = 0; mt < 3; mt++) {
            CP_ASYNC16(st + mt * MAT_SZ + cr0 * LDA_S + cc0,
                       src[mt] + (size_t)cr0 * Dn + ps * 32 + (cc0 >> 1));
            CP_ASYNC16(st + mt * MAT_SZ + cr1 * LDA_S + cc0,
                       src[mt] + (size_t)cr1 * Dn + ps * 32 + (cc0 >> 1));
        }
        CP_COMMIT();
    }

#pragma unroll 1
    for (int s = 0; s < 32; s++) {
        CP_WAIT1();
        __syncthreads();

        const uint32_t stg = sb + (s & 1) * STG_SZ;
#pragma unroll
        for (int ks = 0; ks < 2; ks++) {
            uint32_t ah[2][4], bh[4][4], bl[4][4];
#pragma unroll
            for (int mf = 0; mf < 2; mf++) {
                const uint32_t ao = stg + (a_row + mf * 16) * LDA_S + ks * 32 + a_byt;
                ldsm_x4(ah[mf], ao);
            }
#pragma unroll
            for (int nq = 0; nq < 4; nq++) {
                const uint32_t bo = stg + MAT_SZ +
                                    (b_row + nq * 16) * LDA_S + ks * 32 + b_byt;
                ldsm_x4(bh[nq], bo);
                ldsm_x4(bl[nq], bo + MAT_SZ);
            }
#pragma unroll
            for (int nq = 0; nq < 4; nq++)
#pragma unroll
                for (int mf = 0; mf < 2; mf++) {
                    mma16816h(acc[mf][nq * 2 + 0], ah[mf], bh[nq][0], bh[nq][1]);
                    mma16816h(acc[mf][nq * 2 + 1], ah[mf], bh[nq][2], bh[nq][3]);
                }
#pragma unroll
            for (int nq = 0; nq < 4; nq++)
#pragma unroll
                for (int mf = 0; mf < 2; mf++) {
                    mma16816h(acc[mf][nq * 2 + 0], ah[mf], bl[nq][0], bl[nq][1]);
                    mma16816h(acc[mf][nq * 2 + 1], ah[mf], bl[nq][2], bl[nq][3]);
                }
        }

        __syncthreads();
        if (s + 2 < 32) {
            const uint32_t st = sb + (s & 1) * STG_SZ;
            const int k8 = (s + 2) * 32 + (cc0 >> 1);
#pragma unroll
            for (int mt = 0; mt < 3; mt++) {
                CP_ASYNC16(st + mt * MAT_SZ + cr0 * LDA_S + cc0,
                           src[mt] + (size_t)cr0 * Dn + k8);
                CP_ASYNC16(st + mt * MAT_SZ + cr1 * LDA_S + cc0,
                           src[mt] + (size_t)cr1 * Dn + k8);
            }
        }
        CP_COMMIT();
    }

#pragma unroll
    for (int mf = 0; mf < 2; mf++) {
        const int mr = m0 + wm * 32 + mf * 16 + (lane >> 2);
#pragma unroll
        for (int nf = 0; nf < 8; nf++) {
            const int c0 = n0 + wn * 64 + nf * 8 + (lane & 3) * 2;
            const float b0 = bias[c0], b1 = bias[c0 + 1];
#pragma unroll
            for (int rr = 0; rr < 2; rr++) {
                const int m = mr + rr * 8;
                float v0 = acc[mf][nf][rr * 2 + 0] + b0;
                float v1 = acc[mf][nf][rr * 2 + 1] + b1;
                if (MODE) {
                    v0 *= oscale; v1 *= oscale;
                    const int b = m >> 11, srow = m & (Sn - 1);
                    const int h = c0 >> 6, dk = c0 & 63;
                    const size_t idx =
                        (((size_t)(b * Hn + h)) * Sn + srow) * DKn + dk;
                    *(uint32_t*)(Yh + idx) = packh2(v0, v1);
                } else {
                    float* dst = Yf + (size_t)m * Dn + c0;
                    dst[0] = v0; dst[1] = v1;
                }
            }
        }
    }
}

__global__ __launch_bounds__(256, 2) void gemm_proj(GemmJob a, GemmJob b, GemmJob c)
{
    extern __shared__ char sm[];
    GemmJob j = (blockIdx.z == 0) ? a : ((blockIdx.z == 1) ? b : c);
    gemm_body<1>(j.X, j.Wh, j.Wl, j.bias, nullptr, j.Y, j.oscale, sm);
}

__global__ __launch_bounds__(256, 2) void gemm_out(
    const __half* X, const __half* Wh, const __half* Wl,
    const float* bias, float* Yf)
{
    extern __shared__ char sm[];
    gemm_body<0>(X, Wh, Wl, bias, Yf, nullptr, 1.0f, sm);
}

// ---------------------------------------------------------------------------
// fp16 HMMA causal flash attention, single-precision Q, K, V.
// 128 q-rows per CTA, KV tiles of 64, cp.async double-buffered, 2 CTAs/SM.
// Scores in log2 domain (Q pre-scaled by 0.125*log2e), fexp2 softmax.
// ---------------------------------------------------------------------------
#define LDS_B   144
#define QMAT    18432                  // 128 * 144 (single Q)
#define KVMAT   9216                   // 64 * 144
#define KV_STG  (2 * KVMAT)            // 18432: Kf, Vf
#define ATTN_SMEM (2 * KV_STG)         // 36864 (Q staged in buf1 then reused)

__global__ __launch_bounds__(256, 2) void attn_tc()
{
    extern __shared__ char smem[];
    const uint32_t sb = smem_u32(smem);
    const int tid = threadIdx.x, lane = tid & 31, wid = tid >> 5;

    const int qt = 15 - blockIdx.x;       // heavy blocks first
    const int bh = blockIdx.y;
    const int q0 = qt * 128;

    const size_t base = (size_t)bh * Sn * DKn;
    const __half* Qf = g_Qf + base;
    const __half* Kf = g_Kf + base;
    const __half* Vf = g_Vf + base;

    // ---- stage Q (single fp16) into buf1, pull into A-frags ----
    {
        char* qd = smem + KV_STG;
#pragma unroll
        for (int i = 0; i < 4; i++) {
            const int c = tid + i * 256;        // 1024 chunks of 16B
            const int row = c >> 3, ch = c & 7;
            *(uint4*)(qd + row * LDS_B + ch * 16) =
                *(const uint4*)(Qf + (size_t)(q0 + row) * DKn + ch * 8);
        }
    }
    __syncthreads();

    uint32_t qf[4][4];
    {
        const uint32_t arow = wid * 16 + (lane & 15);
        const uint32_t abyt = (lane >> 4) * 16;
#pragma unroll
        for (int kc = 0; kc < 4; kc++)
            ldsm_x4(qf[kc], sb + KV_STG + arow * LDS_B + kc * 32 + abyt);
    }

    float accO[8][4];
#pragma unroll
    for (int j = 0; j < 8; j++)
#pragma unroll
        for (int k = 0; k < 4; k++) accO[j][k] = 0.f;
    float m_lo = -1e30f, m_hi = -1e30f, l_lo = 0.f, l_hi = 0.f;

    const int r_lo = q0 + wid * 16 + (lane >> 2);
    const int r_hi = r_lo + 8;
    const uint32_t brow = (lane & 7) + ((lane >> 4) << 3);
    const uint32_t bbyt = ((lane >> 3) & 1) * 16;
    const uint32_t vbyt = (lane >> 4) * 16;

    const int ntiles = 2 * qt + 2;

    const int lr = tid >> 3;              // 0..31
    const int lc = (tid & 7) * 16;
    const int le = lc >> 1;

    {
        const uint32_t st = sb;
#pragma unroll
        for (int rr = 0; rr < 2; rr++) {
            const int row = lr + rr * 32;
            const uint32_t so = row * LDS_B + lc;
            const size_t go = (size_t)row * DKn + le;
            CP_ASYNC16(st + 0 * KVMAT + so, Kf + go);
            CP_ASYNC16(st + 1 * KVMAT + so, Vf + go);
        }
        CP_COMMIT();
    }

#pragma unroll 1
    for (int kt = 0; kt < ntiles; kt++) {
        CP_WAIT0();
        __syncthreads();

        if (kt + 1 < ntiles) {
            const uint32_t st = sb + ((kt + 1) & 1) * KV_STG;
#pragma unroll
            for (int rr = 0; rr < 2; rr++) {
                const int row = lr + rr * 32;
                const uint32_t so = row * LDS_B + lc;
                const size_t go = (size_t)((kt + 1) * 64 + row) * DKn + le;
                CP_ASYNC16(st + 0 * KVMAT + so, Kf + go);
                CP_ASYNC16(st + 1 * KVMAT + so, Vf + go);
            }
        }
        CP_COMMIT();

        const uint32_t stg = sb + (kt & 1) * KV_STG;
        const int k0 = kt * 64;

        // ---- S = Q K^T (single fp16), log2-domain scores ----
        float s[8][4];
#pragma unroll
        for (int j = 0; j < 8; j++)
#pragma unroll
            for (int k = 0; k < 4; k++) s[j][k] = 0.f;

#pragma unroll
        for (int kc = 0; kc < 4; kc++) {
#pragma unroll
            for (int nq = 0; nq < 4; nq++) {
                const uint32_t bo = stg + (brow + nq * 16) * LDS_B + kc * 32 + bbyt;
                uint32_t kh[4];
                ldsm_x4(kh, bo);
                mma16816h(s[nq * 2 + 0], qf[kc], kh[0], kh[1]);
                mma16816h(s[nq * 2 + 1], qf[kc], kh[2], kh[3]);
            }
        }

        // ---- causal mask ----
        if ((k0 + 63) > r_lo) {
#pragma unroll
            for (int j = 0; j < 8; j++) {
                const int c = k0 + j * 8 + (lane & 3) * 2;
                if (c > r_lo)     s[j][0] = -1e30f;
                if (c + 1 > r_lo) s[j][1] = -1e30f;
                if (c > r_hi)     s[j][2] = -1e30f;
                if (c + 1 > r_hi) s[j][3] = -1e30f;
            }
        }

        // ---- online softmax (base-2) ----
        float mx0 = -1e30f, mx1 = -1e30f;
#pragma unroll
        for (int j = 0; j < 8; j++) {
            mx0 = fmaxf(mx0, fmaxf(s[j][0], s[j][1]));
            mx1 = fmaxf(mx1, fmaxf(s[j][2], s[j][3]));
        }
        mx0 = fmaxf(mx0, __shfl_xor_sync(0xffffffffu, mx0, 1));
        mx0 = fmaxf(mx0, __shfl_xor_sync(0xffffffffu, mx0, 2));
        mx1 = fmaxf(mx1, __shfl_xor_sync(0xffffffffu, mx1, 1));
        mx1 = fmaxf(mx1, __shfl_xor_sync(0xffffffffu, mx1, 2));
        const float mn0 = fmaxf(m_lo, mx0);
        const float mn1 = fmaxf(m_hi, mx1);
        const float a0 = fexp2(m_lo - mn0);
        const float a1 = fexp2(m_hi - mn1);
        m_lo = mn0; m_hi = mn1;

        float sum0 = 0.f, sum1 = 0.f;
#pragma unroll
        for (int j = 0; j < 8; j++) {
            s[j][0] = fexp2(s[j][0] - mn0);
            s[j][1] = fexp2(s[j][1] - mn0);
            s[j][2] = fexp2(s[j][2] - mn1);
            s[j][3] = fexp2(s[j][3] - mn1);
            sum0 += s[j][0] + s[j][1];
            sum1 += s[j][2] + s[j][3];
        }
        sum0 += __shfl_xor_sync(0xffffffffu, sum0, 1);
        sum0 += __shfl_xor_sync(0xffffffffu, sum0, 2);
        sum1 += __shfl_xor_sync(0xffffffffu, sum1, 1);
        sum1 += __shfl_xor_sync(0xffffffffu, sum1, 2);
        l_lo = l_lo * a0 + sum0;
        l_hi = l_hi * a1 + sum1;
#pragma unroll
        for (int j = 0; j < 8; j++) {
            accO[j][0] *= a0; accO[j][1] *= a0;
            accO[j][2] *= a1; accO[j][3] *= a1;
        }

        // ---- O += P V (single fp16) ----
#pragma unroll
        for (int kc = 0; kc < 4; kc++) {
            uint32_t ph[4];
            ph[0] = packh2(s[2 * kc][0],     s[2 * kc][1]);
            ph[1] = packh2(s[2 * kc][2],     s[2 * kc][3]);
            ph[2] = packh2(s[2 * kc + 1][0], s[2 * kc + 1][1]);
            ph[3] = packh2(s[2 * kc + 1][2], s[2 * kc + 1][3]);
            const uint32_t vrow = kc * 16 + (lane & 15);
#pragma unroll
            for (int np = 0; np < 4; np++) {
                const uint32_t vo = stg + KVMAT + vrow * LDS_B + np * 32 + vbyt;
                uint32_t vh[4];
                ldsm_x4_t(vh, vo);
                mma16816h(accO[np * 2 + 0], ph, vh[0], vh[1]);
                mma16816h(accO[np * 2 + 1], ph, vh[2], vh[3]);
            }
        }
    }

    // ---- epilogue: normalize, write single fp16 [B,S,D] ----
    const float il0 = 1.0f / l_lo;
    const float il1 = 1.0f / l_hi;
    const int b = bh >> 4, h = bh & 15;
    const int c_base = h * DKn + (lane & 3) * 2;
#pragma unroll
    for (int j = 0; j < 8; j++) {
        const int c = c_base + j * 8;
        const size_t i0 = ((size_t)(b * Sn + r_lo)) * Dn + c;
        const size_t i1 = ((size_t)(b * Sn + r_hi)) * Dn + c;
        *(uint32_t*)(g_Af + i0) = packh2(accO[j][0] * il0, accO[j][1] * il0);
        *(uint32_t*)(g_Af + i1) = packh2(accO[j][2] * il1, accO[j][3] * il1);
    }
}

// ---------------------------------------------------------------------------
extern "C" void kernel_launch(void* const* d_in, const int* in_sizes, int n_in,
                              void* d_out, int out_size)
{
    const float* k_in = (const float*)d_in[0];
    const float* q_in = (const float*)d_in[1];
    const float* v_in = (const float*)d_in[2];
    const float* w_q  = (const float*)d_in[3];
    const float* b_q  = (const float*)d_in[4];
    const float* w_k  = (const float*)d_in[5];
    const float* b_k  = (const float*)d_in[6];
    const float* w_v  = (const float*)d_in[7];
    const float* b_v  = (const float*)d_in[8];
    const float* w_o  = (const float*)d_in[9];
    const float* b_o  = (const float*)d_in[10];
    float* out = (float*)d_out;

    __half *xq, *xk, *xv;
    __half *wqh, *wql, *wkh, *wkl, *wvh, *wvl, *woh, *wol;
    __half *Qf, *Kf, *Vf, *Af;
    cudaGetSymbolAddress((void**)&xq, g_xq);
    cudaGetSymbolAddress((void**)&xk, g_xk);
    cudaGetSymbolAddress((void**)&xv, g_xv);
    cudaGetSymbolAddress((void**)&wqh, g_wqh); cudaGetSymbolAddress((void**)&wql, g_wql);
    cudaGetSymbolAddress((void**)&wkh, g_wkh); cudaGetSymbolAddress((void**)&wkl, g_wkl);
    cudaGetSymbolAddress((void**)&wvh, g_wvh); cudaGetSymbolAddress((void**)&wvl, g_wvl);
    cudaGetSymbolAddress((void**)&woh, g_woh); cudaGetSymbolAddress((void**)&wol, g_wol);
    cudaGetSymbolAddress((void**)&Qf, g_Qf);
    cudaGetSymbolAddress((void**)&Kf, g_Kf);
    cudaGetSymbolAddress((void**)&Vf, g_Vf);
    cudaGetSymbolAddress((void**)&Af, g_Af);

    cudaFuncSetAttribute(gemm_proj, cudaFuncAttributeMaxDynamicSharedMemorySize,
                         GEMM_SMEM);
    cudaFuncSetAttribute(gemm_out, cudaFuncAttributeMaxDynamicSharedMemorySize,
                         GEMM_SMEM);
    cudaFuncSetAttribute(attn_tc, cudaFuncAttributeMaxDynamicSharedMemorySize,
                         ATTN_SMEM);

    // one-launch conversion prepass
    conv_all<<<dim3(1024, 7), 256>>>(
        q_in, k_in, v_in, w_q, w_k, w_v, w_o,
        xq, xk, xv,
        wqh, wql, wkh, wkl, wvh, wvl, woh, wol);

    // merged Q/K/V projection GEMMs (all single fp16 out; Q pre-scaled)
    GemmJob jq = { xq, wqh, wql, b_q, Qf, 0.125f * 1.4426950408889634f };
    GemmJob jk = { xk, wkh, wkl, b_k, Kf, 1.0f };
    GemmJob jv = { xv, wvh, wvl, b_v, Vf, 1.0f };
    gemm_proj<<<dim3(32, 8, 3), 256, GEMM_SMEM>>>(jq, jk, jv);

    attn_tc<<<dim3(16, 32), 256, ATTN_SMEM>>>();

    gemm_out<<<dim3(32, 8), 256, GEMM_SMEM>>>(Af, woh, wol, b_o, out);
}

// round 15
// speedup vs baseline: 2.1616x; 1.3019x over previous
#include <cuda_runtime.h>
#include <cuda_bf16.h>
#include <cuda_fp16.h>
#include <cstdint>

#define Bn 2
#define Sn 2048
#define Dn 1024
#define Hn 16
#define DKn 64

#define NELEM (4096 * 1024)
#define WELEM (1024 * 1024)

// Scratch (device globals; no allocations allowed) -- all single fp16.
__device__ __half g_xq[NELEM], g_xk[NELEM], g_xv[NELEM];
__device__ __half g_wq[WELEM], g_wk[WELEM], g_wv[WELEM], g_wo[WELEM];
__device__ __half g_Qf[NELEM];                 // [B,H,S,DK] pre-scaled
__device__ __half g_Kf[NELEM];
__device__ __half g_Vf[NELEM];
__device__ __half g_Af[NELEM];                 // attn out [B,S,D]

// ---------------------------------------------------------------------------
// Helpers
// ---------------------------------------------------------------------------
__device__ __forceinline__ uint32_t smem_u32(const void* p) {
    uint32_t a;
    asm("{ .reg .u64 t; cvta.to.shared.u64 t, %1; cvt.u32.u64 %0, t; }"
        : "=r"(a) : "l"(p));
    return a;
}

__device__ __forceinline__ void ldsm_x4(uint32_t (&r)[4], uint32_t addr) {
    asm volatile("ldmatrix.sync.aligned.m8n8.x4.shared.b16 {%0,%1,%2,%3}, [%4];"
        : "=r"(r[0]), "=r"(r[1]), "=r"(r[2]), "=r"(r[3]) : "r"(addr));
}

__device__ __forceinline__ void ldsm_x4_t(uint32_t (&r)[4], uint32_t addr) {
    asm volatile("ldmatrix.sync.aligned.m8n8.x4.trans.shared.b16 {%0,%1,%2,%3}, [%4];"
        : "=r"(r[0]), "=r"(r[1]), "=r"(r[2]), "=r"(r[3]) : "r"(addr));
}

// fp16 MMA
__device__ __forceinline__ void mma16816h(float (&d)[4], const uint32_t (&a)[4],
                                          uint32_t b0, uint32_t b1) {
    asm volatile(
        "mma.sync.aligned.m16n8k16.row.col.f32.f16.f16.f32 "
        "{%0,%1,%2,%3}, {%4,%5,%6,%7}, {%8,%9}, {%0,%1,%2,%3};"
        : "+f"(d[0]), "+f"(d[1]), "+f"(d[2]), "+f"(d[3])
        : "r"(a[0]), "r"(a[1]), "r"(a[2]), "r"(a[3]), "r"(b0), "r"(b1));
}

#define CP_ASYNC16(dst, src) \
    asm volatile("cp.async.cg.shared.global [%0], [%1], 16;" \
                 :: "r"(dst), "l"(src) : "memory")
#define CP_COMMIT()  asm volatile("cp.async.commit_group;" ::: "memory")
#define CP_WAIT0()   asm volatile("cp.async.wait_group 0;" ::: "memory")
#define CP_WAIT1()   asm volatile("cp.async.wait_group 1;" ::: "memory")

// fp16 pack (single) of a float4
__device__ __forceinline__ uint2 pack4h(float4 v) {
    uint2 o;
    o.x = ((uint32_t)__half_as_ushort(__float2half_rn(v.y)) << 16) |
          __half_as_ushort(__float2half_rn(v.x));
    o.y = ((uint32_t)__half_as_ushort(__float2half_rn(v.w)) << 16) |
          __half_as_ushort(__float2half_rn(v.z));
    return o;
}

__device__ __forceinline__ uint32_t packh2(float a, float b) {
    return ((uint32_t)__half_as_ushort(__float2half_rn(b)) << 16) |
           __half_as_ushort(__float2half_rn(a));
}

// Fast 2^x on the FMA pipe. Valid for x <= 0 (clamped at -126). |err|~2.4e-6.
__device__ __forceinline__ float fexp2(float x) {
    x = fmaxf(x, -126.0f);
    float n = rintf(x);
    float r = x - n;
    float p = fmaf(r, 1.3333558e-3f, 9.6181291e-3f);
    p = fmaf(r, p, 5.5504109e-2f);
    p = fmaf(r, p, 2.4022651e-1f);
    p = fmaf(r, p, 6.9314718e-1f);
    p = fmaf(r, p, 1.0f);
    int e = ((int)n + 127) << 23;
    return p * __int_as_float(e);
}

// ---------------------------------------------------------------------------
// Prepass: all 7 tensors -> single fp16. One launch.
// ---------------------------------------------------------------------------
__global__ __launch_bounds__(256) void conv_all(
    const float* __restrict__ q, const float* __restrict__ k,
    const float* __restrict__ v,
    const float* __restrict__ wq, const float* __restrict__ wk,
    const float* __restrict__ wv, const float* __restrict__ wo,
    __half* xq, __half* xk, __half* xv,
    __half* dwq, __half* dwk, __half* dwv, __half* dwo)
{
    const int z = blockIdx.y;
    const float* src;
    __half* H;
    int n4;
    switch (z) {
        case 0: src = q;  H = xq;  n4 = NELEM / 4; break;
        case 1: src = k;  H = xk;  n4 = NELEM / 4; break;
        case 2: src = v;  H = xv;  n4 = NELEM / 4; break;
        case 3: src = wq; H = dwq; n4 = WELEM / 4; break;
        case 4: src = wk; H = dwk; n4 = WELEM / 4; break;
        case 5: src = wv; H = dwv; n4 = WELEM / 4; break;
        default: src = wo; H = dwo; n4 = WELEM / 4; break;
    }
    const int base = blockIdx.x * 1024 + threadIdx.x;
    if (base >= n4) return;
#pragma unroll
    for (int u = 0; u < 4; u++) {
        const int i = base + u * 256;
        if (i < n4)
            ((uint2*)H)[i] = pack4h(((const float4*)src)[i]);
    }
}

// ---------------------------------------------------------------------------
// fp16 HMMA GEMM body, single-term (X*W), cp.async 2-stage, 2 CTAs/SM.
// MODE 1: single fp16 out permuted [B,H,S,DK]. MODE 0: fp32 row-major out.
// ---------------------------------------------------------------------------
#define LDA_S   80
#define MAT_SZ  (128 * LDA_S)            // 10240
#define STG_SZ  (2 * MAT_SZ)             // 20480: X, W
#define GEMM_SMEM (2 * STG_SZ)           // 40960

struct GemmJob {
    const __half *X, *W;
    const float* bias;
    __half *Y;
    float oscale;
};

template <int MODE>
__device__ __forceinline__ void gemm_body(
    const __half* __restrict__ X,
    const __half* __restrict__ W,
    const float* __restrict__ bias,
    float* __restrict__ Yf,
    __half* __restrict__ Yh,
    float oscale, char* sm)
{
    const uint32_t sb = smem_u32(sm);
    const int tid  = threadIdx.x;
    const int lane = tid & 31;
    const int wid  = tid >> 5;
    const int wm   = wid >> 1;
    const int wn   = wid & 1;

    const int m0 = blockIdx.x * 128;
    const int n0 = blockIdx.y * 128;
    const __half* src[2] = { X + (size_t)m0 * Dn, W + (size_t)n0 * Dn };

    const int cr0 = (tid + 0)   >> 2;
    const int cc0 = (tid & 3)   * 16;
    const int cr1 = (tid + 256) >> 2;

    const uint32_t a_row = wm * 32 + (lane & 15);
    const uint32_t a_byt = (lane >> 4) * 16;
    const uint32_t b_row = wn * 64 + (lane & 7) + ((lane >> 4) << 3);
    const uint32_t b_byt = ((lane >> 3) & 1) * 16;

    float acc[2][8][4];
#pragma unroll
    for (int i = 0; i < 2; i++)
#pragma unroll
        for (int j = 0; j < 8; j++)
#pragma unroll
            for (int k = 0; k < 4; k++) acc[i][j][k] = 0.f;

#pragma unroll
    for (int ps = 0; ps < 2; ps++) {
        const uint32_t st = sb + ps * STG_SZ;
#pragma unroll
        for (int mt = 0; mt < 2; mt++) {
            CP_ASYNC16(st + mt * MAT_SZ + cr0 * LDA_S + cc0,
                       src[mt] + (size_t)cr0 * Dn + ps * 32 + (cc0 >> 1));
            CP_ASYNC16(st + mt * MAT_SZ + cr1 * LDA_S + cc0,
                       src[mt] + (size_t)cr1 * Dn + ps * 32 + (cc0 >> 1));
        }
        CP_COMMIT();
    }

#pragma unroll 1
    for (int s = 0; s < 32; s++) {
        CP_WAIT1();
        __syncthreads();

        const uint32_t stg = sb + (s & 1) * STG_SZ;
#pragma unroll
        for (int ks = 0; ks < 2; ks++) {
            uint32_t ah[2][4], bh[4][4];
#pragma unroll
            for (int mf = 0; mf < 2; mf++) {
                const uint32_t ao = stg + (a_row + mf * 16) * LDA_S + ks * 32 + a_byt;
                ldsm_x4(ah[mf], ao);
            }
#pragma unroll
            for (int nq = 0; nq < 4; nq++) {
                const uint32_t bo = stg + MAT_SZ +
                                    (b_row + nq * 16) * LDA_S + ks * 32 + b_byt;
                ldsm_x4(bh[nq], bo);
            }
#pragma unroll
            for (int nq = 0; nq < 4; nq++)
#pragma unroll
                for (int mf = 0; mf < 2; mf++) {
                    mma16816h(acc[mf][nq * 2 + 0], ah[mf], bh[nq][0], bh[nq][1]);
                    mma16816h(acc[mf][nq * 2 + 1], ah[mf], bh[nq][2], bh[nq][3]);
                }
        }

        __syncthreads();
        if (s + 2 < 32) {
            const uint32_t st = sb + (s & 1) * STG_SZ;
            const int k8 = (s + 2) * 32 + (cc0 >> 1);
#pragma unroll
            for (int mt = 0; mt < 2; mt++) {
                CP_ASYNC16(st + mt * MAT_SZ + cr0 * LDA_S + cc0,
                           src[mt] + (size_t)cr0 * Dn + k8);
                CP_ASYNC16(st + mt * MAT_SZ + cr1 * LDA_S + cc0,
                           src[mt] + (size_t)cr1 * Dn + k8);
            }
        }
        CP_COMMIT();
    }

#pragma unroll
    for (int mf = 0; mf < 2; mf++) {
        const int mr = m0 + wm * 32 + mf * 16 + (lane >> 2);
#pragma unroll
        for (int nf = 0; nf < 8; nf++) {
            const int c0 = n0 + wn * 64 + nf * 8 + (lane & 3) * 2;
            const float b0 = bias[c0], b1 = bias[c0 + 1];
#pragma unroll
            for (int rr = 0; rr < 2; rr++) {
                const int m = mr + rr * 8;
                float v0 = acc[mf][nf][rr * 2 + 0] + b0;
                float v1 = acc[mf][nf][rr * 2 + 1] + b1;
                if (MODE) {
                    v0 *= oscale; v1 *= oscale;
                    const int b = m >> 11, srow = m & (Sn - 1);
                    const int h = c0 >> 6, dk = c0 & 63;
                    const size_t idx =
                        (((size_t)(b * Hn + h)) * Sn + srow) * DKn + dk;
                    *(uint32_t*)(Yh + idx) = packh2(v0, v1);
                } else {
                    float* dst = Yf + (size_t)m * Dn + c0;
                    dst[0] = v0; dst[1] = v1;
                }
            }
        }
    }
}

__global__ __launch_bounds__(256, 2) void gemm_proj(GemmJob a, GemmJob b, GemmJob c)
{
    extern __shared__ char sm[];
    GemmJob j = (blockIdx.z == 0) ? a : ((blockIdx.z == 1) ? b : c);
    gemm_body<1>(j.X, j.W, j.bias, nullptr, j.Y, j.oscale, sm);
}

__global__ __launch_bounds__(256, 2) void gemm_out(
    const __half* X, const __half* W, const float* bias, float* Yf)
{
    extern __shared__ char sm[];
    gemm_body<0>(X, W, bias, Yf, nullptr, 1.0f, sm);
}

// ---------------------------------------------------------------------------
// fp16 HMMA causal flash attention, single-precision Q, K, V (unchanged).
// 128 q-rows per CTA, KV tiles of 64, cp.async double-buffered, 2 CTAs/SM.
// Scores in log2 domain (Q pre-scaled by 0.125*log2e), fexp2 softmax.
// ---------------------------------------------------------------------------
#define LDS_B   144
#define QMAT    18432                  // 128 * 144 (single Q)
#define KVMAT   9216                   // 64 * 144
#define KV_STG  (2 * KVMAT)            // 18432: Kf, Vf
#define ATTN_SMEM (2 * KV_STG)         // 36864 (Q staged in buf1 then reused)

__global__ __launch_bounds__(256, 2) void attn_tc()
{
    extern __shared__ char smem[];
    const uint32_t sb = smem_u32(smem);
    const int tid = threadIdx.x, lane = tid & 31, wid = tid >> 5;

    const int qt = 15 - blockIdx.x;       // heavy blocks first
    const int bh = blockIdx.y;
    const int q0 = qt * 128;

    const size_t base = (size_t)bh * Sn * DKn;
    const __half* Qf = g_Qf + base;
    const __half* Kf = g_Kf + base;
    const __half* Vf = g_Vf + base;

    // ---- stage Q (single fp16) into buf1, pull into A-frags ----
    {
        char* qd = smem + KV_STG;
#pragma unroll
        for (int i = 0; i < 4; i++) {
            const int c = tid + i * 256;        // 1024 chunks of 16B
            const int row = c >> 3, ch = c & 7;
            *(uint4*)(qd + row * LDS_B + ch * 16) =
                *(const uint4*)(Qf + (size_t)(q0 + row) * DKn + ch * 8);
        }
    }
    __syncthreads();

    uint32_t qf[4][4];
    {
        const uint32_t arow = wid * 16 + (lane & 15);
        const uint32_t abyt = (lane >> 4) * 16;
#pragma unroll
        for (int kc = 0; kc < 4; kc++)
            ldsm_x4(qf[kc], sb + KV_STG + arow * LDS_B + kc * 32 + abyt);
    }

    float accO[8][4];
#pragma unroll
    for (int j = 0; j < 8; j++)
#pragma unroll
        for (int k = 0; k < 4; k++) accO[j][k] = 0.f;
    float m_lo = -1e30f, m_hi = -1e30f, l_lo = 0.f, l_hi = 0.f;

    const int r_lo = q0 + wid * 16 + (lane >> 2);
    const int r_hi = r_lo + 8;
    const uint32_t brow = (lane & 7) + ((lane >> 4) << 3);
    const uint32_t bbyt = ((lane >> 3) & 1) * 16;
    const uint32_t vbyt = (lane >> 4) * 16;

    const int ntiles = 2 * qt + 2;

    const int lr = tid >> 3;              // 0..31
    const int lc = (tid & 7) * 16;
    const int le = lc >> 1;

    {
        const uint32_t st = sb;
#pragma unroll
        for (int rr = 0; rr < 2; rr++) {
            const int row = lr + rr * 32;
            const uint32_t so = row * LDS_B + lc;
            const size_t go = (size_t)row * DKn + le;
            CP_ASYNC16(st + 0 * KVMAT + so, Kf + go);
            CP_ASYNC16(st + 1 * KVMAT + so, Vf + go);
        }
        CP_COMMIT();
    }

#pragma unroll 1
    for (int kt = 0; kt < ntiles; kt++) {
        CP_WAIT0();
        __syncthreads();

        if (kt + 1 < ntiles) {
            const uint32_t st = sb + ((kt + 1) & 1) * KV_STG;
#pragma unroll
            for (int rr = 0; rr < 2; rr++) {
                const int row = lr + rr * 32;
                const uint32_t so = row * LDS_B + lc;
                const size_t go = (size_t)((kt + 1) * 64 + row) * DKn + le;
                CP_ASYNC16(st + 0 * KVMAT + so, Kf + go);
                CP_ASYNC16(st + 1 * KVMAT + so, Vf + go);
            }
        }
        CP_COMMIT();

        const uint32_t stg = sb + (kt & 1) * KV_STG;
        const int k0 = kt * 64;

        // ---- S = Q K^T, log2-domain scores ----
        float s[8][4];
#pragma unroll
        for (int j = 0; j < 8; j++)
#pragma unroll
            for (int k = 0; k < 4; k++) s[j][k] = 0.f;

#pragma unroll
        for (int kc = 0; kc < 4; kc++) {
#pragma unroll
            for (int nq = 0; nq < 4; nq++) {
                const uint32_t bo = stg + (brow + nq * 16) * LDS_B + kc * 32 + bbyt;
                uint32_t kh[4];
                ldsm_x4(kh, bo);
                mma16816h(s[nq * 2 + 0], qf[kc], kh[0], kh[1]);
                mma16816h(s[nq * 2 + 1], qf[kc], kh[2], kh[3]);
            }
        }

        // ---- causal mask ----
        if ((k0 + 63) > r_lo) {
#pragma unroll
            for (int j = 0; j < 8; j++) {
                const int c = k0 + j * 8 + (lane & 3) * 2;
                if (c > r_lo)     s[j][0] = -1e30f;
                if (c + 1 > r_lo) s[j][1] = -1e30f;
                if (c > r_hi)     s[j][2] = -1e30f;
                if (c + 1 > r_hi) s[j][3] = -1e30f;
            }
        }

        // ---- online softmax (base-2) ----
        float mx0 = -1e30f, mx1 = -1e30f;
#pragma unroll
        for (int j = 0; j < 8; j++) {
            mx0 = fmaxf(mx0, fmaxf(s[j][0], s[j][1]));
            mx1 = fmaxf(mx1, fmaxf(s[j][2], s[j][3]));
        }
        mx0 = fmaxf(mx0, __shfl_xor_sync(0xffffffffu, mx0, 1));
        mx0 = fmaxf(mx0, __shfl_xor_sync(0xffffffffu, mx0, 2));
        mx1 = fmaxf(mx1, __shfl_xor_sync(0xffffffffu, mx1, 1));
        mx1 = fmaxf(mx1, __shfl_xor_sync(0xffffffffu, mx1, 2));
        const float mn0 = fmaxf(m_lo, mx0);
        const float mn1 = fmaxf(m_hi, mx1);
        const float a0 = fexp2(m_lo - mn0);
        const float a1 = fexp2(m_hi - mn1);
        m_lo = mn0; m_hi = mn1;

        float sum0 = 0.f, sum1 = 0.f;
#pragma unroll
        for (int j = 0; j < 8; j++) {
            s[j][0] = fexp2(s[j][0] - mn0);
            s[j][1] = fexp2(s[j][1] - mn0);
            s[j][2] = fexp2(s[j][2] - mn1);
            s[j][3] = fexp2(s[j][3] - mn1);
            sum0 += s[j][0] + s[j][1];
            sum1 += s[j][2] + s[j][3];
        }
        sum0 += __shfl_xor_sync(0xffffffffu, sum0, 1);
        sum0 += __shfl_xor_sync(0xffffffffu, sum0, 2);
        sum1 += __shfl_xor_sync(0xffffffffu, sum1, 1);
        sum1 += __shfl_xor_sync(0xffffffffu, sum1, 2);
        l_lo = l_lo * a0 + sum0;
        l_hi = l_hi * a1 + sum1;
#pragma unroll
        for (int j = 0; j < 8; j++) {
            accO[j][0] *= a0; accO[j][1] *= a0;
            accO[j][2] *= a1; accO[j][3] *= a1;
        }

        // ---- O += P V ----
#pragma unroll
        for (int kc = 0; kc < 4; kc++) {
            uint32_t ph[4];
            ph[0] = packh2(s[2 * kc][0],     s[2 * kc][1]);
            ph[1] = packh2(s[2 * kc][2],     s[2 * kc][3]);
            ph[2] = packh2(s[2 * kc + 1][0], s[2 * kc + 1][1]);
            ph[3] = packh2(s[2 * kc + 1][2], s[2 * kc + 1][3]);
            const uint32_t vrow = kc * 16 + (lane & 15);
#pragma unroll
            for (int np = 0; np < 4; np++) {
                const uint32_t vo = stg + KVMAT + vrow * LDS_B + np * 32 + vbyt;
                uint32_t vh[4];
                ldsm_x4_t(vh, vo);
                mma16816h(accO[np * 2 + 0], ph, vh[0], vh[1]);
                mma16816h(accO[np * 2 + 1], ph, vh[2], vh[3]);
            }
        }
    }

    // ---- epilogue: normalize, write single fp16 [B,S,D] ----
    const float il0 = 1.0f / l_lo;
    const float il1 = 1.0f / l_hi;
    const int b = bh >> 4, h = bh & 15;
    const int c_base = h * DKn + (lane & 3) * 2;
#pragma unroll
    for (int j = 0; j < 8; j++) {
        const int c = c_base + j * 8;
        const size_t i0 = ((size_t)(b * Sn + r_lo)) * Dn + c;
        const size_t i1 = ((size_t)(b * Sn + r_hi)) * Dn + c;
        *(uint32_t*)(g_Af + i0) = packh2(accO[j][0] * il0, accO[j][1] * il0);
        *(uint32_t*)(g_Af + i1) = packh2(accO[j][2] * il1, accO[j][3] * il1);
    }
}

// ---------------------------------------------------------------------------
extern "C" void kernel_launch(void* const* d_in, const int* in_sizes, int n_in,
                              void* d_out, int out_size)
{
    const float* k_in = (const float*)d_in[0];
    const float* q_in = (const float*)d_in[1];
    const float* v_in = (const float*)d_in[2];
    const float* w_q  = (const float*)d_in[3];
    const float* b_q  = (const float*)d_in[4];
    const float* w_k  = (const float*)d_in[5];
    const float* b_k  = (const float*)d_in[6];
    const float* w_v  = (const float*)d_in[7];
    const float* b_v  = (const float*)d_in[8];
    const float* w_o  = (const float*)d_in[9];
    const float* b_o  = (const float*)d_in[10];
    float* out = (float*)d_out;

    __half *xq, *xk, *xv, *wq, *wk, *wv, *wo;
    __half *Qf, *Kf, *Vf, *Af;
    cudaGetSymbolAddress((void**)&xq, g_xq);
    cudaGetSymbolAddress((void**)&xk, g_xk);
    cudaGetSymbolAddress((void**)&xv, g_xv);
    cudaGetSymbolAddress((void**)&wq, g_wq);
    cudaGetSymbolAddress((void**)&wk, g_wk);
    cudaGetSymbolAddress((void**)&wv, g_wv);
    cudaGetSymbolAddress((void**)&wo, g_wo);
    cudaGetSymbolAddress((void**)&Qf, g_Qf);
    cudaGetSymbolAddress((void**)&Kf, g_Kf);
    cudaGetSymbolAddress((void**)&Vf, g_Vf);
    cudaGetSymbolAddress((void**)&Af, g_Af);

    cudaFuncSetAttribute(gemm_proj, cudaFuncAttributeMaxDynamicSharedMemorySize,
                         GEMM_SMEM);
    cudaFuncSetAttribute(gemm_out, cudaFuncAttributeMaxDynamicSharedMemorySize,
                         GEMM_SMEM);
    cudaFuncSetAttribute(attn_tc, cudaFuncAttributeMaxDynamicSharedMemorySize,
                         ATTN_SMEM);

    // one-launch conversion prepass
    conv_all<<<dim3(1024, 7), 256>>>(
        q_in, k_in, v_in, w_q, w_k, w_v, w_o,
        xq, xk, xv, wq, wk, wv, wo);

    // merged Q/K/V projection GEMMs (single fp16; Q pre-scaled into log2 domain)
    GemmJob jq = { xq, wq, b_q, Qf, 0.125f * 1.4426950408889634f };
    GemmJob jk = { xk, wk, b_k, Kf, 1.0f };
    GemmJob jv = { xv, wv, b_v, Vf, 1.0f };
    gemm_proj<<<dim3(32, 8, 3), 256, GEMM_SMEM>>>(jq, jk, jv);

    attn_tc<<<dim3(16, 32), 256, ATTN_SMEM>>>();

    gemm_out<<<dim3(32, 8), 256, GEMM_SMEM>>>(Af, wo, b_o, out);
}